// round 9
// baseline (speedup 1.0000x reference)
#include <cuda_runtime.h>
#include <cuda_fp16.h>
#include <math.h>
#include <stdint.h>

#define NN 100000
#define NE 1600000
#define DIM 128
#define NB 391   // ceil(NN/256)
#define PADH 72  // padded half-stride for [128][64] SMEM tiles

typedef unsigned long long ull;

// ---- scratch (device globals: no allocation allowed) ----
__device__ __half g_xs[NN*DIM];   // source-side projection x@Wsrc (fp16)
__device__ float g_h [NN*DIM];    // skip (x@linW+lin_b), later h
__device__ float g_x [NN*DIM];    // layer output ping buffer
__device__ float g_s [NN*8];      // per-node attention scores
__device__ __half g_Bh[256*DIM];  // packed [Wsrc|linW] transposed [n][k], fp16 hi
__device__ __half g_Bl[256*DIM];  // fp16 lo residual
__device__ __half g_Fh[384*DIM];  // fcW transposed [n][k] fp16 hi (zero-padded)
__device__ __half g_Fl[384*DIM];  // fcW lo residual
__device__ float g_Batt[8*DIM];   // packed (W @ att) vectors
__device__ float g_bn [2*DIM];    // per-channel sum / sumsq
// CSR (built once; graph fixed across layers)
__device__ int g_deg[NN];
__device__ int g_off[NN+1];
__device__ int g_pos[NN];
__device__ int g_csr[NE];
__device__ int g_bsum[NB];
__device__ int g_bbase[NB];

#define MMA16816(d, a, b0, b1) \
  asm volatile("mma.sync.aligned.m16n8k16.row.col.f32.f16.f16.f32 " \
               "{%0,%1,%2,%3}, {%4,%5,%6,%7}, {%8,%9}, {%0,%1,%2,%3};" \
               : "+f"((d)[0]), "+f"((d)[1]), "+f"((d)[2]), "+f"((d)[3]) \
               : "r"((a)[0]), "r"((a)[1]), "r"((a)[2]), "r"((a)[3]), \
                 "r"(b0), "r"(b1))

// ==================== CSR build ====================
__global__ void k_zero_deg() {
  int i = blockIdx.x*blockDim.x + threadIdx.x;
  if (i < NN) g_deg[i] = 0;
}
__global__ void k_hist(const int* __restrict__ dst) {
  int e = blockIdx.x*blockDim.x + threadIdx.x;
  if (e < NE) atomicAdd(&g_deg[dst[e]], 1);
}
__global__ void k_blockred() {
  __shared__ int sh[256];
  int t = threadIdx.x;
  int i = blockIdx.x*256 + t;
  sh[t] = (i < NN) ? g_deg[i] : 0;
  __syncthreads();
  for (int o = 128; o; o >>= 1) { if (t < o) sh[t] += sh[t+o]; __syncthreads(); }
  if (t == 0) g_bsum[blockIdx.x] = sh[0];
}
__global__ void k_scanb() {
  __shared__ int sh[512];
  int t = threadIdx.x;
  sh[t] = (t < NB) ? g_bsum[t] : 0;
  __syncthreads();
  for (int off = 1; off < 512; off <<= 1) {
    int v = 0;
    if (t >= off) v = sh[t-off];
    __syncthreads();
    sh[t] += v;
    __syncthreads();
  }
  if (t < NB) g_bbase[t] = sh[t] - g_bsum[t];   // exclusive
}
__global__ void k_off() {
  __shared__ int sh[256];
  int t = threadIdx.x;
  int i = blockIdx.x*256 + t;
  int v = (i < NN) ? g_deg[i] : 0;
  sh[t] = v;
  __syncthreads();
  for (int off = 1; off < 256; off <<= 1) {
    int u = 0;
    if (t >= off) u = sh[t-off];
    __syncthreads();
    sh[t] += u;
    __syncthreads();
  }
  int excl = sh[t] - v + g_bbase[blockIdx.x];
  if (i < NN) { g_off[i] = excl; g_pos[i] = excl; }
  if (i == NN-1) g_off[NN] = excl + v;
}
__global__ void k_scatter(const int* __restrict__ src, const int* __restrict__ dst) {
  int e = blockIdx.x*blockDim.x + threadIdx.x;
  if (e >= NE) return;
  int p = atomicAdd(&g_pos[dst[e]], 1);
  g_csr[p] = src[e];
}

// ---- pack per-layer weights: fp16 hi/lo transposed [n][k]; att vecs; zero BN ----
__global__ void pack_weights(const float* __restrict__ Wsrc,
                             const float* __restrict__ Wdst,
                             const float* __restrict__ linW,
                             const float* __restrict__ asrc,
                             const float* __restrict__ adst) {
  int idx = blockIdx.x*blockDim.x + threadIdx.x;
  if (idx < 256*DIM) {
    int n = idx >> 7, k = idx & 127;
    float v = (n < 128) ? Wsrc[k*128 + n] : linW[k*128 + (n-128)];
    __half hi = __float2half_rn(v);
    __half lo = __float2half_rn(v - __half2float(hi));
    g_Bh[idx] = hi;
    g_Bl[idx] = lo;
  } else if (idx < 256*DIM + 8*DIM) {
    int r = idx - 256*DIM;
    int t = r >> 7, k = r & 127;
    int h = t & 3;
    const float* W = (t < 4) ? Wsrc : Wdst;
    const float* a = (t < 4) ? asrc : adst;
    float s = 0.f;
    #pragma unroll
    for (int c = 0; c < 32; c++) s += W[k*128 + h*32 + c] * a[h*32 + c];
    g_Batt[t*128 + k] = s;
  } else if (idx < 256*DIM + 8*DIM + 2*DIM) {
    g_bn[idx - (256*DIM + 8*DIM)] = 0.f;
  }
}

// ---- pack FC weights (once): fcW [128][349] -> [384][128] fp16 hi/lo ----
__global__ void pack_fc(const float* __restrict__ fcW) {
  int idx = blockIdx.x*blockDim.x + threadIdx.x;
  if (idx >= 384*DIM) return;
  int n = idx >> 7, k = idx & 127;
  float v = (n < 349) ? fcW[k*349 + n] : 0.f;
  __half hi = __float2half_rn(v);
  __half lo = __float2half_rn(v - __half2float(hi));
  g_Fh[idx] = hi;
  g_Fl[idx] = lo;
}

// ==================== HMMA GEMM (K split into 2 slices of 64) ====================
#define HM_SMEM (4*128*PADH*2)   // 73728 B

__global__ void __launch_bounds__(256) gemm_hmma(
    const float* __restrict__ A,
    const __half* __restrict__ Bhg, const __half* __restrict__ Blg,
    float* __restrict__ C, int NC,
    const float* __restrict__ bias, int mode)
{
  extern __shared__ __half sh[];
  __half* Ah  = sh;
  __half* Al  = sh + 128*PADH;
  __half* Bhs = sh + 2*128*PADH;
  __half* Bls = sh + 3*128*PADH;
  const int tid = threadIdx.x;
  const int m0 = blockIdx.y * 128;
  const int n0 = blockIdx.x * 128;

  const int wid = tid >> 5, t = tid & 31;
  const int wm = (wid & 3) * 32;
  const int wn = (wid >> 2) * 64;
  const int tr = t >> 2, tc = (t & 3) * 2;

  float d[2][8][4];
#pragma unroll
  for (int i = 0; i < 2; i++)
#pragma unroll
    for (int j = 0; j < 8; j++)
#pragma unroll
      for (int q = 0; q < 4; q++) d[i][j][q] = 0.f;

  for (int k0 = 0; k0 < 128; k0 += 64) {
    for (int idx = tid; idx < 2048; idx += 256) {
      int r = idx >> 4, c = (idx & 15) * 4;
      float4 v = (m0 + r < NN) ? *(const float4*)&A[(size_t)(m0 + r)*128 + k0 + c]
                               : make_float4(0,0,0,0);
      __half hx = __float2half_rn(v.x), hy = __float2half_rn(v.y);
      __half hz = __float2half_rn(v.z), hw = __float2half_rn(v.w);
      *(__half2*)&Ah[r*PADH + c]     = __halves2half2(hx, hy);
      *(__half2*)&Ah[r*PADH + c + 2] = __halves2half2(hz, hw);
      __half lx = __float2half_rn(v.x - __half2float(hx));
      __half ly = __float2half_rn(v.y - __half2float(hy));
      __half lz = __float2half_rn(v.z - __half2float(hz));
      __half lw = __float2half_rn(v.w - __half2float(hw));
      *(__half2*)&Al[r*PADH + c]     = __halves2half2(lx, ly);
      *(__half2*)&Al[r*PADH + c + 2] = __halves2half2(lz, lw);
    }
    for (int idx = tid; idx < 2048; idx += 256) {
      int n = idx >> 4, k = (idx & 15) * 4;
      *(uint2*)&Bhs[n*PADH + k] = *(const uint2*)&Bhg[(size_t)(n0 + n)*128 + k0 + k];
      *(uint2*)&Bls[n*PADH + k] = *(const uint2*)&Blg[(size_t)(n0 + n)*128 + k0 + k];
    }
    __syncthreads();

#pragma unroll
    for (int kk = 0; kk < 4; kk++) {
      const int kc = kk*16 + tc;
      uint32_t ah[2][4], alr[2][4];
#pragma unroll
      for (int i = 0; i < 2; i++) {
        int r0 = wm + i*16 + tr;
        ah[i][0]  = *(uint32_t*)&Ah[r0*PADH + kc];
        ah[i][1]  = *(uint32_t*)&Ah[(r0+8)*PADH + kc];
        ah[i][2]  = *(uint32_t*)&Ah[r0*PADH + kc + 8];
        ah[i][3]  = *(uint32_t*)&Ah[(r0+8)*PADH + kc + 8];
        alr[i][0] = *(uint32_t*)&Al[r0*PADH + kc];
        alr[i][1] = *(uint32_t*)&Al[(r0+8)*PADH + kc];
        alr[i][2] = *(uint32_t*)&Al[r0*PADH + kc + 8];
        alr[i][3] = *(uint32_t*)&Al[(r0+8)*PADH + kc + 8];
      }
#pragma unroll
      for (int j = 0; j < 8; j++) {
        int n = wn + j*8 + tr;
        uint32_t bh0 = *(uint32_t*)&Bhs[n*PADH + kc];
        uint32_t bh1 = *(uint32_t*)&Bhs[n*PADH + kc + 8];
        uint32_t bl0 = *(uint32_t*)&Bls[n*PADH + kc];
        uint32_t bl1 = *(uint32_t*)&Bls[n*PADH + kc + 8];
#pragma unroll
        for (int i = 0; i < 2; i++) {
          MMA16816(d[i][j], ah[i],  bh0, bh1);
          MMA16816(d[i][j], ah[i],  bl0, bl1);
          MMA16816(d[i][j], alr[i], bh0, bh1);
        }
      }
    }
    __syncthreads();
  }

#pragma unroll
  for (int i = 0; i < 2; i++) {
    int r0 = m0 + wm + i*16 + tr;
#pragma unroll
    for (int j = 0; j < 8; j++) {
      int col = wn + j*8 + tc;
      if (mode == 1) {
        if (n0 == 0) {
          if (r0 < NN)
            *(__half2*)&g_xs[(size_t)r0*128 + col] = __floats2half2_rn(d[i][j][0], d[i][j][1]);
          if (r0 + 8 < NN)
            *(__half2*)&g_xs[(size_t)(r0+8)*128 + col] = __floats2half2_rn(d[i][j][2], d[i][j][3]);
        } else {
          float b0v = bias[col], b1v = bias[col+1];
          if (r0 < NN) {
            g_h[(size_t)r0*128 + col]     = d[i][j][0] + b0v;
            g_h[(size_t)r0*128 + col + 1] = d[i][j][1] + b1v;
          }
          if (r0 + 8 < NN) {
            g_h[(size_t)(r0+8)*128 + col]     = d[i][j][2] + b0v;
            g_h[(size_t)(r0+8)*128 + col + 1] = d[i][j][3] + b1v;
          }
        }
      } else {
        int c = n0 + col;
        if (c < NC) {
          float bv = bias[c];
          if (r0 < NN)     C[(size_t)r0*NC + c]     = d[i][j][0] + bv;
          if (r0 + 8 < NN) C[(size_t)(r0+8)*NC + c] = d[i][j][2] + bv;
        }
        if (c + 1 < NC) {
          float bv = bias[c+1];
          if (r0 < NN)     C[(size_t)r0*NC + c + 1]     = d[i][j][1] + bv;
          if (r0 + 8 < NN) C[(size_t)(r0+8)*NC + c + 1] = d[i][j][3] + bv;
        }
      }
    }
  }
}

// ---- per-node attention scores ----
__global__ void __launch_bounds__(256) att_scores(const float* __restrict__ X) {
  int gw = (blockIdx.x*blockDim.x + threadIdx.x) >> 5;
  if (gw >= NN) return;
  int lane = threadIdx.x & 31;
  float4 xv = *(const float4*)&X[(size_t)gw*128 + lane*4];
#pragma unroll
  for (int t = 0; t < 8; t++) {
    float4 w = *(const float4*)&g_Batt[t*128 + lane*4];
    float p = xv.x*w.x + xv.y*w.y + xv.z*w.z + xv.w*w.w;
#pragma unroll
    for (int off = 16; off; off >>= 1) p += __shfl_xor_sync(0xffffffffu, p, off);
    if (lane == 0) g_s[(size_t)gw*8 + t] = p;
  }
}

// ---- gather: softmax + aggregate + bias + skip + BN stats; 4-edge pipeline ----
__global__ void __launch_bounds__(256) gather_combine(const float* __restrict__ cbias) {
  __shared__ float s_sum[128], s_sq[128];
  int tid = threadIdx.x;
  if (tid < 128) { s_sum[tid] = 0.f; s_sq[tid] = 0.f; }
  __syncthreads();
  int warp = tid >> 5, lane = tid & 31;
  int n = blockIdx.x*8 + warp;
  int head = lane >> 3, c4 = lane*4;
  float h0=0,h1=0,h2=0,h3=0;
  bool valid = (n < NN);
  if (valid) {
    int beg = g_off[n], end = g_off[n+1];
    float sd = g_s[(size_t)n*8 + 4 + head];
    float ax=0.f, ay=0.f, az=0.f, aw=0.f, den=0.f;
    int i = beg;
    for (; i + 4 <= end; i += 4) {
      // batch 4 indices, then 4 scores + 4 rows (8-9 loads in flight)
      int s0 = g_csr[i], s1 = g_csr[i+1], s2 = g_csr[i+2], s3 = g_csr[i+3];
      float e0 = g_s[(size_t)s0*8 + head];
      float e1 = g_s[(size_t)s1*8 + head];
      float e2 = g_s[(size_t)s2*8 + head];
      float e3 = g_s[(size_t)s3*8 + head];
      uint2 u0 = *(const uint2*)&g_xs[(size_t)s0*128 + c4];
      uint2 u1 = *(const uint2*)&g_xs[(size_t)s1*128 + c4];
      uint2 u2 = *(const uint2*)&g_xs[(size_t)s2*128 + c4];
      uint2 u3 = *(const uint2*)&g_xs[(size_t)s3*128 + c4];
      e0 += sd; e1 += sd; e2 += sd; e3 += sd;
      e0 = (e0 > 0.f) ? e0 : 0.2f*e0;
      e1 = (e1 > 0.f) ? e1 : 0.2f*e1;
      e2 = (e2 > 0.f) ? e2 : 0.2f*e2;
      e3 = (e3 > 0.f) ? e3 : 0.2f*e3;
      float p0 = __expf(e0), p1 = __expf(e1), p2 = __expf(e2), p3 = __expf(e3);
      den += (p0 + p1) + (p2 + p3);
      float2 a0 = __half22float2(*reinterpret_cast<__half2*>(&u0.x));
      float2 b0 = __half22float2(*reinterpret_cast<__half2*>(&u0.y));
      float2 a1 = __half22float2(*reinterpret_cast<__half2*>(&u1.x));
      float2 b1 = __half22float2(*reinterpret_cast<__half2*>(&u1.y));
      float2 a2 = __half22float2(*reinterpret_cast<__half2*>(&u2.x));
      float2 b2 = __half22float2(*reinterpret_cast<__half2*>(&u2.y));
      float2 a3 = __half22float2(*reinterpret_cast<__half2*>(&u3.x));
      float2 b3 = __half22float2(*reinterpret_cast<__half2*>(&u3.y));
      ax = fmaf(a0.x, p0, ax); ay = fmaf(a0.y, p0, ay);
      az = fmaf(b0.x, p0, az); aw = fmaf(b0.y, p0, aw);
      ax = fmaf(a1.x, p1, ax); ay = fmaf(a1.y, p1, ay);
      az = fmaf(b1.x, p1, az); aw = fmaf(b1.y, p1, aw);
      ax = fmaf(a2.x, p2, ax); ay = fmaf(a2.y, p2, ay);
      az = fmaf(b2.x, p2, az); aw = fmaf(b2.y, p2, aw);
      ax = fmaf(a3.x, p3, ax); ay = fmaf(a3.y, p3, ay);
      az = fmaf(b3.x, p3, az); aw = fmaf(b3.y, p3, aw);
    }
    for (; i < end; i++) {
      int s = g_csr[i];
      float ev = g_s[(size_t)s*8 + head] + sd;
      ev = (ev > 0.f) ? ev : 0.2f*ev;
      float p = __expf(ev);
      den += p;
      uint2 u = *(const uint2*)&g_xs[(size_t)s*128 + c4];
      float2 f0 = __half22float2(*reinterpret_cast<__half2*>(&u.x));
      float2 f1 = __half22float2(*reinterpret_cast<__half2*>(&u.y));
      ax = fmaf(f0.x, p, ax); ay = fmaf(f0.y, p, ay);
      az = fmaf(f1.x, p, az); aw = fmaf(f1.y, p, aw);
    }
    float inv = 1.f / (den + 1e-16f);
    float4 cb = *(const float4*)&cbias[c4];
    float4 sk = *(const float4*)&g_h[(size_t)n*128 + c4];
    h0 = ax*inv + cb.x + sk.x;
    h1 = ay*inv + cb.y + sk.y;
    h2 = az*inv + cb.z + sk.z;
    h3 = aw*inv + cb.w + sk.w;
    *(float4*)&g_h[(size_t)n*128 + c4] = make_float4(h0,h1,h2,h3);
  }
  if (valid) {
    atomicAdd(&s_sum[c4+0], h0); atomicAdd(&s_sum[c4+1], h1);
    atomicAdd(&s_sum[c4+2], h2); atomicAdd(&s_sum[c4+3], h3);
    atomicAdd(&s_sq[c4+0], h0*h0); atomicAdd(&s_sq[c4+1], h1*h1);
    atomicAdd(&s_sq[c4+2], h2*h2); atomicAdd(&s_sq[c4+3], h3*h3);
  }
  __syncthreads();
  if (tid < 128) {
    atomicAdd(&g_bn[tid],       s_sum[tid]);
    atomicAdd(&g_bn[128 + tid], s_sq[tid]);
  }
}

// ---- batchnorm + relu ----
__global__ void __launch_bounds__(256) bn_relu(const float* __restrict__ gamma,
                                               const float* __restrict__ beta,
                                               float* __restrict__ XO) {
  int idx = blockIdx.x*blockDim.x + threadIdx.x;
  if (idx >= NN*32) return;
  int c4 = (idx & 31) * 4;
  const float invN = 1.f / (float)NN;
  float4 h = *(const float4*)&g_h[(size_t)idx*4];
  float hv[4] = {h.x, h.y, h.z, h.w};
  float ov[4];
#pragma unroll
  for (int k = 0; k < 4; k++) {
    int c = c4 + k;
    float mu  = g_bn[c] * invN;
    float var = g_bn[128 + c] * invN - mu*mu;
    float sc  = gamma[c] * rsqrtf(var + 1e-5f);
    float sh  = beta[c] - mu*sc;
    float v = hv[k]*sc + sh;
    ov[k] = v > 0.f ? v : 0.f;
  }
  *(float4*)&XO[(size_t)idx*4] = make_float4(ov[0],ov[1],ov[2],ov[3]);
}

extern "C" void kernel_launch(void* const* d_in, const int* in_sizes, int n_in,
                              void* d_out, int out_size) {
  const float* x0    = (const float*)d_in[0];
  const int*   ei    = (const int*)  d_in[1];
  const float* Wsrc  = (const float*)d_in[2];
  const float* Wdst  = (const float*)d_in[3];
  const float* asrc  = (const float*)d_in[4];
  const float* adst  = (const float*)d_in[5];
  const float* cbias = (const float*)d_in[6];
  const float* linW  = (const float*)d_in[7];
  const float* linb  = (const float*)d_in[8];
  const float* gamma = (const float*)d_in[9];
  const float* beta  = (const float*)d_in[10];
  const float* fcW   = (const float*)d_in[11];
  const float* fcb   = (const float*)d_in[12];
  float* out = (float*)d_out;

  float *xg = 0;
  __half *Bh = 0, *Bl = 0, *Fh = 0, *Fl = 0;
  cudaGetSymbolAddress((void**)&xg, g_x);
  cudaGetSymbolAddress((void**)&Bh, g_Bh);
  cudaGetSymbolAddress((void**)&Bl, g_Bl);
  cudaGetSymbolAddress((void**)&Fh, g_Fh);
  cudaGetSymbolAddress((void**)&Fl, g_Fl);
  cudaFuncSetAttribute(gemm_hmma, cudaFuncAttributeMaxDynamicSharedMemorySize, HM_SMEM);

  const int* src = ei;
  const int* dst = ei + NE;

  // launch index 3 (the one ncu profiles) = gemm_hmma
  k_zero_deg<<<NB, 256>>>();
  k_hist<<<(NE+255)/256, 256>>>(dst);
  pack_weights<<<134, 256>>>(Wsrc, Wdst, linW, asrc, adst);
  gemm_hmma<<<dim3(2, 782), 256, HM_SMEM>>>(x0, Bh, Bl, nullptr, 0, linb, 1); // profiled
  pack_fc<<<192, 256>>>(fcW);
  k_blockred<<<NB, 256>>>();
  k_scanb<<<1, 512>>>();
  k_off<<<NB, 256>>>();
  k_scatter<<<(NE+255)/256, 256>>>(src, dst);
  att_scores<<<12500, 256>>>(x0);
  gather_combine<<<12500, 256>>>(cbias);
  bn_relu<<<12500, 256>>>(gamma, beta, xg);

  pack_weights<<<134, 256>>>(Wsrc + 16384, Wdst + 16384, linW + 16384,
                             asrc + 128, adst + 128);
  gemm_hmma<<<dim3(2, 782), 256, HM_SMEM>>>(xg, Bh, Bl, nullptr, 0, linb + 128, 1);
  att_scores<<<12500, 256>>>(xg);
  gather_combine<<<12500, 256>>>(cbias + 128);
  bn_relu<<<12500, 256>>>(gamma + 128, beta + 128, xg);

  gemm_hmma<<<dim3(3, 782), 256, HM_SMEM>>>(xg, Fh, Fl, out, 349, fcb, 0);
}

// round 10
// speedup vs baseline: 1.1732x; 1.1732x over previous
#include <cuda_runtime.h>
#include <cuda_fp16.h>
#include <math.h>
#include <stdint.h>

#define NN 100000
#define NE 1600000
#define DIM 128
#define NB 391   // ceil(NN/256)
#define PADH 72  // padded half-stride for [128][64] SMEM tiles

typedef unsigned long long ull;

// ---- scratch (device globals: no allocation allowed) ----
__device__ __half g_xs[NN*DIM];   // source-side projection x@Wsrc (fp16)
__device__ float g_h [NN*DIM];    // skip (x@linW+lin_b), later h
__device__ float g_x [NN*DIM];    // layer output ping buffer
__device__ float g_s [NN*8];      // per-node attention scores
__device__ __half g_Bh[256*DIM];  // packed [Wsrc|linW] transposed [n][k], fp16 hi
__device__ __half g_Bl[256*DIM];  // fp16 lo residual
__device__ __half g_Fh[384*DIM];  // fcW transposed [n][k] fp16 hi (zero-padded)
__device__ __half g_Fl[384*DIM];  // fcW lo residual
__device__ float g_Batt[8*DIM];   // packed (W @ att) vectors
__device__ float g_bn [2*DIM];    // per-channel sum / sumsq
__device__ int   g_work;          // work-stealing cursor for gather
// CSR (built once; graph fixed across layers)
__device__ int g_deg[NN];
__device__ int g_off[NN+1];
__device__ int g_pos[NN];
__device__ int g_csr[NE];
__device__ int g_bsum[NB];
__device__ int g_bbase[NB];

#define MMA16816(d, a, b0, b1) \
  asm volatile("mma.sync.aligned.m16n8k16.row.col.f32.f16.f16.f32 " \
               "{%0,%1,%2,%3}, {%4,%5,%6,%7}, {%8,%9}, {%0,%1,%2,%3};" \
               : "+f"((d)[0]), "+f"((d)[1]), "+f"((d)[2]), "+f"((d)[3]) \
               : "r"((a)[0]), "r"((a)[1]), "r"((a)[2]), "r"((a)[3]), \
                 "r"(b0), "r"(b1))

// ==================== CSR build ====================
__global__ void k_zero_deg() {
  int i = blockIdx.x*blockDim.x + threadIdx.x;
  if (i < NN) g_deg[i] = 0;
}
__global__ void k_hist(const int* __restrict__ dst) {
  int e = blockIdx.x*blockDim.x + threadIdx.x;
  if (e < NE) atomicAdd(&g_deg[dst[e]], 1);
}
__global__ void k_blockred() {
  __shared__ int sh[256];
  int t = threadIdx.x;
  int i = blockIdx.x*256 + t;
  sh[t] = (i < NN) ? g_deg[i] : 0;
  __syncthreads();
  for (int o = 128; o; o >>= 1) { if (t < o) sh[t] += sh[t+o]; __syncthreads(); }
  if (t == 0) g_bsum[blockIdx.x] = sh[0];
}
__global__ void k_scanb() {
  __shared__ int sh[512];
  int t = threadIdx.x;
  sh[t] = (t < NB) ? g_bsum[t] : 0;
  __syncthreads();
  for (int off = 1; off < 512; off <<= 1) {
    int v = 0;
    if (t >= off) v = sh[t-off];
    __syncthreads();
    sh[t] += v;
    __syncthreads();
  }
  if (t < NB) g_bbase[t] = sh[t] - g_bsum[t];   // exclusive
}
__global__ void k_off() {
  __shared__ int sh[256];
  int t = threadIdx.x;
  int i = blockIdx.x*256 + t;
  int v = (i < NN) ? g_deg[i] : 0;
  sh[t] = v;
  __syncthreads();
  for (int off = 1; off < 256; off <<= 1) {
    int u = 0;
    if (t >= off) u = sh[t-off];
    __syncthreads();
    sh[t] += u;
    __syncthreads();
  }
  int excl = sh[t] - v + g_bbase[blockIdx.x];
  if (i < NN) { g_off[i] = excl; g_pos[i] = excl; }
  if (i == NN-1) g_off[NN] = excl + v;
}
__global__ void k_scatter(const int* __restrict__ src, const int* __restrict__ dst) {
  int e = blockIdx.x*blockDim.x + threadIdx.x;
  if (e >= NE) return;
  int p = atomicAdd(&g_pos[dst[e]], 1);
  g_csr[p] = src[e];
}

// ---- pack per-layer weights: fp16 hi/lo transposed [n][k]; att vecs; zero BN ----
__global__ void pack_weights(const float* __restrict__ Wsrc,
                             const float* __restrict__ Wdst,
                             const float* __restrict__ linW,
                             const float* __restrict__ asrc,
                             const float* __restrict__ adst) {
  int idx = blockIdx.x*blockDim.x + threadIdx.x;
  if (idx == 0) g_work = 0;
  if (idx < 256*DIM) {
    int n = idx >> 7, k = idx & 127;
    float v = (n < 128) ? Wsrc[k*128 + n] : linW[k*128 + (n-128)];
    __half hi = __float2half_rn(v);
    __half lo = __float2half_rn(v - __half2float(hi));
    g_Bh[idx] = hi;
    g_Bl[idx] = lo;
  } else if (idx < 256*DIM + 8*DIM) {
    int r = idx - 256*DIM;
    int t = r >> 7, k = r & 127;
    int h = t & 3;
    const float* W = (t < 4) ? Wsrc : Wdst;
    const float* a = (t < 4) ? asrc : adst;
    float s = 0.f;
    #pragma unroll
    for (int c = 0; c < 32; c++) s += W[k*128 + h*32 + c] * a[h*32 + c];
    g_Batt[t*128 + k] = s;
  } else if (idx < 256*DIM + 8*DIM + 2*DIM) {
    g_bn[idx - (256*DIM + 8*DIM)] = 0.f;
  }
}

// ---- pack FC weights (once): fcW [128][349] -> [384][128] fp16 hi/lo ----
__global__ void pack_fc(const float* __restrict__ fcW) {
  int idx = blockIdx.x*blockDim.x + threadIdx.x;
  if (idx >= 384*DIM) return;
  int n = idx >> 7, k = idx & 127;
  float v = (n < 349) ? fcW[k*349 + n] : 0.f;
  __half hi = __float2half_rn(v);
  __half lo = __float2half_rn(v - __half2float(hi));
  g_Fh[idx] = hi;
  g_Fl[idx] = lo;
}

// ==================== HMMA GEMM (K split into 2 slices of 64) ====================
#define HM_SMEM (4*128*PADH*2)   // 73728 B

__global__ void __launch_bounds__(256) gemm_hmma(
    const float* __restrict__ A,
    const __half* __restrict__ Bhg, const __half* __restrict__ Blg,
    float* __restrict__ C, int NC,
    const float* __restrict__ bias, int mode)
{
  extern __shared__ __half sh[];
  __half* Ah  = sh;
  __half* Al  = sh + 128*PADH;
  __half* Bhs = sh + 2*128*PADH;
  __half* Bls = sh + 3*128*PADH;
  const int tid = threadIdx.x;
  const int m0 = blockIdx.y * 128;
  const int n0 = blockIdx.x * 128;

  const int wid = tid >> 5, t = tid & 31;
  const int wm = (wid & 3) * 32;
  const int wn = (wid >> 2) * 64;
  const int tr = t >> 2, tc = (t & 3) * 2;

  float d[2][8][4];
#pragma unroll
  for (int i = 0; i < 2; i++)
#pragma unroll
    for (int j = 0; j < 8; j++)
#pragma unroll
      for (int q = 0; q < 4; q++) d[i][j][q] = 0.f;

  for (int k0 = 0; k0 < 128; k0 += 64) {
    for (int idx = tid; idx < 2048; idx += 256) {
      int r = idx >> 4, c = (idx & 15) * 4;
      float4 v = (m0 + r < NN) ? *(const float4*)&A[(size_t)(m0 + r)*128 + k0 + c]
                               : make_float4(0,0,0,0);
      __half hx = __float2half_rn(v.x), hy = __float2half_rn(v.y);
      __half hz = __float2half_rn(v.z), hw = __float2half_rn(v.w);
      *(__half2*)&Ah[r*PADH + c]     = __halves2half2(hx, hy);
      *(__half2*)&Ah[r*PADH + c + 2] = __halves2half2(hz, hw);
      __half lx = __float2half_rn(v.x - __half2float(hx));
      __half ly = __float2half_rn(v.y - __half2float(hy));
      __half lz = __float2half_rn(v.z - __half2float(hz));
      __half lw = __float2half_rn(v.w - __half2float(hw));
      *(__half2*)&Al[r*PADH + c]     = __halves2half2(lx, ly);
      *(__half2*)&Al[r*PADH + c + 2] = __halves2half2(lz, lw);
    }
    for (int idx = tid; idx < 2048; idx += 256) {
      int n = idx >> 4, k = (idx & 15) * 4;
      *(uint2*)&Bhs[n*PADH + k] = *(const uint2*)&Bhg[(size_t)(n0 + n)*128 + k0 + k];
      *(uint2*)&Bls[n*PADH + k] = *(const uint2*)&Blg[(size_t)(n0 + n)*128 + k0 + k];
    }
    __syncthreads();

#pragma unroll
    for (int kk = 0; kk < 4; kk++) {
      const int kc = kk*16 + tc;
      uint32_t ah[2][4], alr[2][4];
#pragma unroll
      for (int i = 0; i < 2; i++) {
        int r0 = wm + i*16 + tr;
        ah[i][0]  = *(uint32_t*)&Ah[r0*PADH + kc];
        ah[i][1]  = *(uint32_t*)&Ah[(r0+8)*PADH + kc];
        ah[i][2]  = *(uint32_t*)&Ah[r0*PADH + kc + 8];
        ah[i][3]  = *(uint32_t*)&Ah[(r0+8)*PADH + kc + 8];
        alr[i][0] = *(uint32_t*)&Al[r0*PADH + kc];
        alr[i][1] = *(uint32_t*)&Al[(r0+8)*PADH + kc];
        alr[i][2] = *(uint32_t*)&Al[r0*PADH + kc + 8];
        alr[i][3] = *(uint32_t*)&Al[(r0+8)*PADH + kc + 8];
      }
#pragma unroll
      for (int j = 0; j < 8; j++) {
        int n = wn + j*8 + tr;
        uint32_t bh0 = *(uint32_t*)&Bhs[n*PADH + kc];
        uint32_t bh1 = *(uint32_t*)&Bhs[n*PADH + kc + 8];
        uint32_t bl0 = *(uint32_t*)&Bls[n*PADH + kc];
        uint32_t bl1 = *(uint32_t*)&Bls[n*PADH + kc + 8];
#pragma unroll
        for (int i = 0; i < 2; i++) {
          MMA16816(d[i][j], ah[i],  bh0, bh1);
          MMA16816(d[i][j], ah[i],  bl0, bl1);
          MMA16816(d[i][j], alr[i], bh0, bh1);
        }
      }
    }
    __syncthreads();
  }

#pragma unroll
  for (int i = 0; i < 2; i++) {
    int r0 = m0 + wm + i*16 + tr;
#pragma unroll
    for (int j = 0; j < 8; j++) {
      int col = wn + j*8 + tc;
      if (mode == 1) {
        if (n0 == 0) {
          if (r0 < NN)
            *(__half2*)&g_xs[(size_t)r0*128 + col] = __floats2half2_rn(d[i][j][0], d[i][j][1]);
          if (r0 + 8 < NN)
            *(__half2*)&g_xs[(size_t)(r0+8)*128 + col] = __floats2half2_rn(d[i][j][2], d[i][j][3]);
        } else {
          float b0v = bias[col], b1v = bias[col+1];
          if (r0 < NN) {
            g_h[(size_t)r0*128 + col]     = d[i][j][0] + b0v;
            g_h[(size_t)r0*128 + col + 1] = d[i][j][1] + b1v;
          }
          if (r0 + 8 < NN) {
            g_h[(size_t)(r0+8)*128 + col]     = d[i][j][2] + b0v;
            g_h[(size_t)(r0+8)*128 + col + 1] = d[i][j][3] + b1v;
          }
        }
      } else {
        int c = n0 + col;
        if (c < NC) {
          float bv = bias[c];
          if (r0 < NN)     C[(size_t)r0*NC + c]     = d[i][j][0] + bv;
          if (r0 + 8 < NN) C[(size_t)(r0+8)*NC + c] = d[i][j][2] + bv;
        }
        if (c + 1 < NC) {
          float bv = bias[c+1];
          if (r0 < NN)     C[(size_t)r0*NC + c + 1]     = d[i][j][1] + bv;
          if (r0 + 8 < NN) C[(size_t)(r0+8)*NC + c + 1] = d[i][j][3] + bv;
        }
      }
    }
  }
}

// ---- per-node attention scores ----
__global__ void __launch_bounds__(256) att_scores(const float* __restrict__ X) {
  int gw = (blockIdx.x*blockDim.x + threadIdx.x) >> 5;
  if (gw >= NN) return;
  int lane = threadIdx.x & 31;
  float4 xv = *(const float4*)&X[(size_t)gw*128 + lane*4];
#pragma unroll
  for (int t = 0; t < 8; t++) {
    float4 w = *(const float4*)&g_Batt[t*128 + lane*4];
    float p = xv.x*w.x + xv.y*w.y + xv.z*w.z + xv.w*w.w;
#pragma unroll
    for (int off = 16; off; off >>= 1) p += __shfl_xor_sync(0xffffffffu, p, off);
    if (lane == 0) g_s[(size_t)gw*8 + t] = p;
  }
}

// ---- gather: work-stealing warps; BN stats in registers; 4-edge pipeline ----
__global__ void __launch_bounds__(256) gather_combine(const float* __restrict__ cbias) {
  __shared__ float s_sum[128], s_sq[128];
  int tid = threadIdx.x;
  if (tid < 128) { s_sum[tid] = 0.f; s_sq[tid] = 0.f; }
  __syncthreads();
  int lane = tid & 31;
  int head = lane >> 3, c4 = lane*4;
  float4 cb = *(const float4*)&cbias[c4];
  float bs0=0,bs1=0,bs2=0,bs3=0, bq0=0,bq1=0,bq2=0,bq3=0;

  for (;;) {
    int base = 0;
    if (lane == 0) base = atomicAdd(&g_work, 4);
    base = __shfl_sync(0xffffffffu, base, 0);
    if (base >= NN) break;
    int nend = (base + 4 < NN) ? base + 4 : NN;
    for (int n = base; n < nend; n++) {
      int beg = g_off[n], end = g_off[n+1];
      float sd = g_s[(size_t)n*8 + 4 + head];
      float ax=0.f, ay=0.f, az=0.f, aw=0.f, den=0.f;
      int i = beg;
      for (; i + 4 <= end; i += 4) {
        int s0 = g_csr[i], s1 = g_csr[i+1], s2 = g_csr[i+2], s3 = g_csr[i+3];
        float e0 = g_s[(size_t)s0*8 + head];
        float e1 = g_s[(size_t)s1*8 + head];
        float e2 = g_s[(size_t)s2*8 + head];
        float e3 = g_s[(size_t)s3*8 + head];
        uint2 u0 = *(const uint2*)&g_xs[(size_t)s0*128 + c4];
        uint2 u1 = *(const uint2*)&g_xs[(size_t)s1*128 + c4];
        uint2 u2 = *(const uint2*)&g_xs[(size_t)s2*128 + c4];
        uint2 u3 = *(const uint2*)&g_xs[(size_t)s3*128 + c4];
        e0 += sd; e1 += sd; e2 += sd; e3 += sd;
        e0 = (e0 > 0.f) ? e0 : 0.2f*e0;
        e1 = (e1 > 0.f) ? e1 : 0.2f*e1;
        e2 = (e2 > 0.f) ? e2 : 0.2f*e2;
        e3 = (e3 > 0.f) ? e3 : 0.2f*e3;
        float p0 = __expf(e0), p1 = __expf(e1), p2 = __expf(e2), p3 = __expf(e3);
        den += (p0 + p1) + (p2 + p3);
        float2 a0 = __half22float2(*reinterpret_cast<__half2*>(&u0.x));
        float2 b0 = __half22float2(*reinterpret_cast<__half2*>(&u0.y));
        float2 a1 = __half22float2(*reinterpret_cast<__half2*>(&u1.x));
        float2 b1 = __half22float2(*reinterpret_cast<__half2*>(&u1.y));
        float2 a2 = __half22float2(*reinterpret_cast<__half2*>(&u2.x));
        float2 b2 = __half22float2(*reinterpret_cast<__half2*>(&u2.y));
        float2 a3 = __half22float2(*reinterpret_cast<__half2*>(&u3.x));
        float2 b3 = __half22float2(*reinterpret_cast<__half2*>(&u3.y));
        ax = fmaf(a0.x, p0, ax); ay = fmaf(a0.y, p0, ay);
        az = fmaf(b0.x, p0, az); aw = fmaf(b0.y, p0, aw);
        ax = fmaf(a1.x, p1, ax); ay = fmaf(a1.y, p1, ay);
        az = fmaf(b1.x, p1, az); aw = fmaf(b1.y, p1, aw);
        ax = fmaf(a2.x, p2, ax); ay = fmaf(a2.y, p2, ay);
        az = fmaf(b2.x, p2, az); aw = fmaf(b2.y, p2, aw);
        ax = fmaf(a3.x, p3, ax); ay = fmaf(a3.y, p3, ay);
        az = fmaf(b3.x, p3, az); aw = fmaf(b3.y, p3, aw);
      }
      for (; i < end; i++) {
        int s = g_csr[i];
        float ev = g_s[(size_t)s*8 + head] + sd;
        ev = (ev > 0.f) ? ev : 0.2f*ev;
        float p = __expf(ev);
        den += p;
        uint2 u = *(const uint2*)&g_xs[(size_t)s*128 + c4];
        float2 f0 = __half22float2(*reinterpret_cast<__half2*>(&u.x));
        float2 f1 = __half22float2(*reinterpret_cast<__half2*>(&u.y));
        ax = fmaf(f0.x, p, ax); ay = fmaf(f0.y, p, ay);
        az = fmaf(f1.x, p, az); aw = fmaf(f1.y, p, aw);
      }
      float inv = 1.f / (den + 1e-16f);
      float4 sk = *(const float4*)&g_h[(size_t)n*128 + c4];
      float h0 = ax*inv + cb.x + sk.x;
      float h1 = ay*inv + cb.y + sk.y;
      float h2 = az*inv + cb.z + sk.z;
      float h3 = aw*inv + cb.w + sk.w;
      *(float4*)&g_h[(size_t)n*128 + c4] = make_float4(h0,h1,h2,h3);
      bs0 += h0; bs1 += h1; bs2 += h2; bs3 += h3;
      bq0 += h0*h0; bq1 += h1*h1; bq2 += h2*h2; bq3 += h3*h3;
    }
  }
  // one shared-atomic flush per warp
  atomicAdd(&s_sum[c4+0], bs0); atomicAdd(&s_sum[c4+1], bs1);
  atomicAdd(&s_sum[c4+2], bs2); atomicAdd(&s_sum[c4+3], bs3);
  atomicAdd(&s_sq[c4+0], bq0);  atomicAdd(&s_sq[c4+1], bq1);
  atomicAdd(&s_sq[c4+2], bq2);  atomicAdd(&s_sq[c4+3], bq3);
  __syncthreads();
  if (tid < 128) {
    atomicAdd(&g_bn[tid],       s_sum[tid]);
    atomicAdd(&g_bn[128 + tid], s_sq[tid]);
  }
}

// ---- batchnorm + relu ----
__global__ void __launch_bounds__(256) bn_relu(const float* __restrict__ gamma,
                                               const float* __restrict__ beta,
                                               float* __restrict__ XO) {
  int idx = blockIdx.x*blockDim.x + threadIdx.x;
  if (idx >= NN*32) return;
  int c4 = (idx & 31) * 4;
  const float invN = 1.f / (float)NN;
  float4 h = *(const float4*)&g_h[(size_t)idx*4];
  float hv[4] = {h.x, h.y, h.z, h.w};
  float ov[4];
#pragma unroll
  for (int k = 0; k < 4; k++) {
    int c = c4 + k;
    float mu  = g_bn[c] * invN;
    float var = g_bn[128 + c] * invN - mu*mu;
    float sc  = gamma[c] * rsqrtf(var + 1e-5f);
    float sh  = beta[c] - mu*sc;
    float v = hv[k]*sc + sh;
    ov[k] = v > 0.f ? v : 0.f;
  }
  *(float4*)&XO[(size_t)idx*4] = make_float4(ov[0],ov[1],ov[2],ov[3]);
}

extern "C" void kernel_launch(void* const* d_in, const int* in_sizes, int n_in,
                              void* d_out, int out_size) {
  const float* x0    = (const float*)d_in[0];
  const int*   ei    = (const int*)  d_in[1];
  const float* Wsrc  = (const float*)d_in[2];
  const float* Wdst  = (const float*)d_in[3];
  const float* asrc  = (const float*)d_in[4];
  const float* adst  = (const float*)d_in[5];
  const float* cbias = (const float*)d_in[6];
  const float* linW  = (const float*)d_in[7];
  const float* linb  = (const float*)d_in[8];
  const float* gamma = (const float*)d_in[9];
  const float* beta  = (const float*)d_in[10];
  const float* fcW   = (const float*)d_in[11];
  const float* fcb   = (const float*)d_in[12];
  float* out = (float*)d_out;

  float *xg = 0;
  __half *Bh = 0, *Bl = 0, *Fh = 0, *Fl = 0;
  cudaGetSymbolAddress((void**)&xg, g_x);
  cudaGetSymbolAddress((void**)&Bh, g_Bh);
  cudaGetSymbolAddress((void**)&Bl, g_Bl);
  cudaGetSymbolAddress((void**)&Fh, g_Fh);
  cudaGetSymbolAddress((void**)&Fl, g_Fl);
  cudaFuncSetAttribute(gemm_hmma, cudaFuncAttributeMaxDynamicSharedMemorySize, HM_SMEM);

  const int* src = ei;
  const int* dst = ei + NE;

  // launch index 3 (the one ncu profiles) = gemm_hmma
  k_zero_deg<<<NB, 256>>>();
  k_hist<<<(NE+255)/256, 256>>>(dst);
  pack_weights<<<134, 256>>>(Wsrc, Wdst, linW, asrc, adst);
  gemm_hmma<<<dim3(2, 782), 256, HM_SMEM>>>(x0, Bh, Bl, nullptr, 0, linb, 1); // profiled
  pack_fc<<<192, 256>>>(fcW);
  k_blockred<<<NB, 256>>>();
  k_scanb<<<1, 512>>>();
  k_off<<<NB, 256>>>();
  k_scatter<<<(NE+255)/256, 256>>>(src, dst);
  att_scores<<<12500, 256>>>(x0);
  gather_combine<<<740, 256>>>(cbias);
  bn_relu<<<12500, 256>>>(gamma, beta, xg);

  pack_weights<<<134, 256>>>(Wsrc + 16384, Wdst + 16384, linW + 16384,
                             asrc + 128, adst + 128);
  gemm_hmma<<<dim3(2, 782), 256, HM_SMEM>>>(xg, Bh, Bl, nullptr, 0, linb + 128, 1);
  att_scores<<<12500, 256>>>(xg);
  gather_combine<<<740, 256>>>(cbias + 128);
  bn_relu<<<12500, 256>>>(gamma + 128, beta + 128, xg);

  gemm_hmma<<<dim3(3, 782), 256, HM_SMEM>>>(xg, Fh, Fl, out, 349, fcb, 0);
}

// round 11
// speedup vs baseline: 1.2521x; 1.0672x over previous
#include <cuda_runtime.h>
#include <cuda_fp16.h>
#include <math.h>
#include <stdint.h>

#define NN 100000
#define NE 1600000
#define DIM 128
#define NB 391   // ceil(NN/256)
#define PADH 72  // padded half-stride; 144B row stride = 9*16B (cp.async-aligned)

typedef unsigned long long ull;

// ---- scratch (device globals: no allocation allowed) ----
__device__ __half g_xs[NN*DIM];   // source-side projection x@Wsrc (fp16)
__device__ __half g_xh[NN*DIM];   // current layer input, fp16 (GEMM A operand)
__device__ float g_h [NN*DIM];    // skip (x@linW+lin_b), later h
__device__ float g_x [NN*DIM];    // layer output ping buffer (fp32)
__device__ float g_s [NN*8];      // per-node attention scores
__device__ __half g_Bh[256*DIM];  // packed [Wsrc|linW] transposed [n][k], fp16 hi
__device__ __half g_Bl[256*DIM];  // fp16 lo residual
__device__ __half g_Fh[384*DIM];  // fcW transposed [n][k] fp16 hi (zero-padded)
__device__ __half g_Fl[384*DIM];  // fcW lo residual
__device__ float g_Batt[8*DIM];   // packed (W @ att) vectors
__device__ float g_bn [2*DIM];    // per-channel sum / sumsq
__device__ int   g_work;          // work-stealing cursor for gather
// CSR (built once; graph fixed across layers)
__device__ int g_deg[NN];
__device__ int g_off[NN+1];
__device__ int g_pos[NN];
__device__ int g_csr[NE];
__device__ int g_bsum[NB];
__device__ int g_bbase[NB];

#define MMA16816(d, a, b0, b1) \
  asm volatile("mma.sync.aligned.m16n8k16.row.col.f32.f16.f16.f32 " \
               "{%0,%1,%2,%3}, {%4,%5,%6,%7}, {%8,%9}, {%0,%1,%2,%3};" \
               : "+f"((d)[0]), "+f"((d)[1]), "+f"((d)[2]), "+f"((d)[3]) \
               : "r"((a)[0]), "r"((a)[1]), "r"((a)[2]), "r"((a)[3]), \
                 "r"(b0), "r"(b1))

__device__ __forceinline__ void cp16(uint32_t smem, const void* g, uint32_t sz) {
  asm volatile("cp.async.cg.shared.global [%0], [%1], 16, %2;"
               :: "r"(smem), "l"(g), "r"(sz) : "memory");
}

// ==================== CSR build ====================
__global__ void k_zero_deg() {
  int i = blockIdx.x*blockDim.x + threadIdx.x;
  if (i < NN) g_deg[i] = 0;
}
__global__ void k_hist(const int* __restrict__ dst) {
  int e = blockIdx.x*blockDim.x + threadIdx.x;
  if (e < NE) atomicAdd(&g_deg[dst[e]], 1);
}
__global__ void k_blockred() {
  __shared__ int sh[256];
  int t = threadIdx.x;
  int i = blockIdx.x*256 + t;
  sh[t] = (i < NN) ? g_deg[i] : 0;
  __syncthreads();
  for (int o = 128; o; o >>= 1) { if (t < o) sh[t] += sh[t+o]; __syncthreads(); }
  if (t == 0) g_bsum[blockIdx.x] = sh[0];
}
__global__ void k_scanb() {
  __shared__ int sh[512];
  int t = threadIdx.x;
  sh[t] = (t < NB) ? g_bsum[t] : 0;
  __syncthreads();
  for (int off = 1; off < 512; off <<= 1) {
    int v = 0;
    if (t >= off) v = sh[t-off];
    __syncthreads();
    sh[t] += v;
    __syncthreads();
  }
  if (t < NB) g_bbase[t] = sh[t] - g_bsum[t];   // exclusive
}
__global__ void k_off() {
  __shared__ int sh[256];
  int t = threadIdx.x;
  int i = blockIdx.x*256 + t;
  int v = (i < NN) ? g_deg[i] : 0;
  sh[t] = v;
  __syncthreads();
  for (int off = 1; off < 256; off <<= 1) {
    int u = 0;
    if (t >= off) u = sh[t-off];
    __syncthreads();
    sh[t] += u;
    __syncthreads();
  }
  int excl = sh[t] - v + g_bbase[blockIdx.x];
  if (i < NN) { g_off[i] = excl; g_pos[i] = excl; }
  if (i == NN-1) g_off[NN] = excl + v;
}
__global__ void k_scatter(const int* __restrict__ src, const int* __restrict__ dst) {
  int e = blockIdx.x*blockDim.x + threadIdx.x;
  if (e >= NE) return;
  int p = atomicAdd(&g_pos[dst[e]], 1);
  g_csr[p] = src[e];
}

// ---- convert x0 to fp16 (layer-1 GEMM A operand) ----
__global__ void __launch_bounds__(256) k_cvt(const float* __restrict__ X) {
  int idx = blockIdx.x*blockDim.x + threadIdx.x;
  if (idx >= NN*32) return;
  float4 v = *(const float4*)&X[(size_t)idx*4];
  *(__half2*)&g_xh[(size_t)idx*4]     = __floats2half2_rn(v.x, v.y);
  *(__half2*)&g_xh[(size_t)idx*4 + 2] = __floats2half2_rn(v.z, v.w);
}

// ---- pack per-layer weights: fp16 hi/lo transposed [n][k]; att vecs; zero BN ----
__global__ void pack_weights(const float* __restrict__ Wsrc,
                             const float* __restrict__ Wdst,
                             const float* __restrict__ linW,
                             const float* __restrict__ asrc,
                             const float* __restrict__ adst) {
  int idx = blockIdx.x*blockDim.x + threadIdx.x;
  if (idx == 0) g_work = 0;
  if (idx < 256*DIM) {
    int n = idx >> 7, k = idx & 127;
    float v = (n < 128) ? Wsrc[k*128 + n] : linW[k*128 + (n-128)];
    __half hi = __float2half_rn(v);
    __half lo = __float2half_rn(v - __half2float(hi));
    g_Bh[idx] = hi;
    g_Bl[idx] = lo;
  } else if (idx < 256*DIM + 8*DIM) {
    int r = idx - 256*DIM;
    int t = r >> 7, k = r & 127;
    int h = t & 3;
    const float* W = (t < 4) ? Wsrc : Wdst;
    const float* a = (t < 4) ? asrc : adst;
    float s = 0.f;
    #pragma unroll
    for (int c = 0; c < 32; c++) s += W[k*128 + h*32 + c] * a[h*32 + c];
    g_Batt[t*128 + k] = s;
  } else if (idx < 256*DIM + 8*DIM + 2*DIM) {
    g_bn[idx - (256*DIM + 8*DIM)] = 0.f;
  }
}

// ---- pack FC weights (once): fcW [128][349] -> [384][128] fp16 hi/lo ----
__global__ void pack_fc(const float* __restrict__ fcW) {
  int idx = blockIdx.x*blockDim.x + threadIdx.x;
  if (idx >= 384*DIM) return;
  int n = idx >> 7, k = idx & 127;
  float v = (n < 349) ? fcW[k*349 + n] : 0.f;
  __half hi = __float2half_rn(v);
  __half lo = __float2half_rn(v - __half2float(hi));
  g_Fh[idx] = hi;
  g_Fl[idx] = lo;
}

// ==================== HMMA GEMM: 2-pass (A fp16, W hi/lo), cp.async staging ====
#define HM_SMEM (3*128*PADH*2)   // 55296 B

__global__ void __launch_bounds__(256) gemm_hmma(
    const __half* __restrict__ Bhg, const __half* __restrict__ Blg,
    float* __restrict__ C, int NC,
    const float* __restrict__ bias, int mode)
{
  extern __shared__ __half sh[];
  __half* Ahs = sh;
  __half* Bhs = sh + 128*PADH;
  __half* Bls = sh + 2*128*PADH;
  const int tid = threadIdx.x;
  const int m0 = blockIdx.y * 128;
  const int n0 = blockIdx.x * 128;

  uint32_t sA  = (uint32_t)__cvta_generic_to_shared(Ahs);
  uint32_t sBh = (uint32_t)__cvta_generic_to_shared(Bhs);
  uint32_t sBl = (uint32_t)__cvta_generic_to_shared(Bls);

  const int wid = tid >> 5, t = tid & 31;
  const int wm = (wid & 3) * 32;
  const int wn = (wid >> 2) * 64;
  const int tr = t >> 2, tc = (t & 3) * 2;

  float d[2][8][4];
#pragma unroll
  for (int i = 0; i < 2; i++)
#pragma unroll
    for (int j = 0; j < 8; j++)
#pragma unroll
      for (int q = 0; q < 4; q++) d[i][j][q] = 0.f;

  for (int k0 = 0; k0 < 128; k0 += 64) {
    // stage A (fp16, pre-converted) + B hi/lo via cp.async, 16B chunks
    for (int idx = tid; idx < 1024; idx += 256) {
      int r = idx >> 3, c = (idx & 7) * 8;
      uint32_t off = (uint32_t)(r*PADH + c) * 2;
      int row = m0 + r;
      cp16(sA + off, &g_xh[(size_t)row*128 + k0 + c], (row < NN) ? 16u : 0u);
      cp16(sBh + off, &Bhg[(size_t)(n0 + r)*128 + k0 + c], 16u);
      cp16(sBl + off, &Blg[(size_t)(n0 + r)*128 + k0 + c], 16u);
    }
    asm volatile("cp.async.commit_group;" ::: "memory");
    asm volatile("cp.async.wait_group 0;" ::: "memory");
    __syncthreads();

#pragma unroll
    for (int kk = 0; kk < 4; kk++) {
      const int kc = kk*16 + tc;
      uint32_t ah[2][4];
#pragma unroll
      for (int i = 0; i < 2; i++) {
        int r0 = wm + i*16 + tr;
        ah[i][0] = *(uint32_t*)&Ahs[r0*PADH + kc];
        ah[i][1] = *(uint32_t*)&Ahs[(r0+8)*PADH + kc];
        ah[i][2] = *(uint32_t*)&Ahs[r0*PADH + kc + 8];
        ah[i][3] = *(uint32_t*)&Ahs[(r0+8)*PADH + kc + 8];
      }
#pragma unroll
      for (int j = 0; j < 8; j++) {
        int n = wn + j*8 + tr;
        uint32_t bh0 = *(uint32_t*)&Bhs[n*PADH + kc];
        uint32_t bh1 = *(uint32_t*)&Bhs[n*PADH + kc + 8];
        uint32_t bl0 = *(uint32_t*)&Bls[n*PADH + kc];
        uint32_t bl1 = *(uint32_t*)&Bls[n*PADH + kc + 8];
#pragma unroll
        for (int i = 0; i < 2; i++) {
          MMA16816(d[i][j], ah[i], bh0, bh1);
          MMA16816(d[i][j], ah[i], bl0, bl1);
        }
      }
    }
    __syncthreads();
  }

#pragma unroll
  for (int i = 0; i < 2; i++) {
    int r0 = m0 + wm + i*16 + tr;
#pragma unroll
    for (int j = 0; j < 8; j++) {
      int col = wn + j*8 + tc;
      if (mode == 1) {
        if (n0 == 0) {
          if (r0 < NN)
            *(__half2*)&g_xs[(size_t)r0*128 + col] = __floats2half2_rn(d[i][j][0], d[i][j][1]);
          if (r0 + 8 < NN)
            *(__half2*)&g_xs[(size_t)(r0+8)*128 + col] = __floats2half2_rn(d[i][j][2], d[i][j][3]);
        } else {
          float b0v = bias[col], b1v = bias[col+1];
          if (r0 < NN) {
            g_h[(size_t)r0*128 + col]     = d[i][j][0] + b0v;
            g_h[(size_t)r0*128 + col + 1] = d[i][j][1] + b1v;
          }
          if (r0 + 8 < NN) {
            g_h[(size_t)(r0+8)*128 + col]     = d[i][j][2] + b0v;
            g_h[(size_t)(r0+8)*128 + col + 1] = d[i][j][3] + b1v;
          }
        }
      } else {
        int c = n0 + col;
        if (c < NC) {
          float bv = bias[c];
          if (r0 < NN)     C[(size_t)r0*NC + c]     = d[i][j][0] + bv;
          if (r0 + 8 < NN) C[(size_t)(r0+8)*NC + c] = d[i][j][2] + bv;
        }
        if (c + 1 < NC) {
          float bv = bias[c+1];
          if (r0 < NN)     C[(size_t)r0*NC + c + 1]     = d[i][j][1] + bv;
          if (r0 + 8 < NN) C[(size_t)(r0+8)*NC + c + 1] = d[i][j][3] + bv;
        }
      }
    }
  }
}

// ---- per-node attention scores ----
__global__ void __launch_bounds__(256) att_scores(const float* __restrict__ X) {
  int gw = (blockIdx.x*blockDim.x + threadIdx.x) >> 5;
  if (gw >= NN) return;
  int lane = threadIdx.x & 31;
  float4 xv = *(const float4*)&X[(size_t)gw*128 + lane*4];
#pragma unroll
  for (int t = 0; t < 8; t++) {
    float4 w = *(const float4*)&g_Batt[t*128 + lane*4];
    float p = xv.x*w.x + xv.y*w.y + xv.z*w.z + xv.w*w.w;
#pragma unroll
    for (int off = 16; off; off >>= 1) p += __shfl_xor_sync(0xffffffffu, p, off);
    if (lane == 0) g_s[(size_t)gw*8 + t] = p;
  }
}

// ---- gather: work-stealing warps; BN stats in registers; 4-edge pipeline ----
__global__ void __launch_bounds__(256) gather_combine(const float* __restrict__ cbias) {
  __shared__ float s_sum[128], s_sq[128];
  int tid = threadIdx.x;
  if (tid < 128) { s_sum[tid] = 0.f; s_sq[tid] = 0.f; }
  __syncthreads();
  int lane = tid & 31;
  int head = lane >> 3, c4 = lane*4;
  float4 cb = *(const float4*)&cbias[c4];
  float bs0=0,bs1=0,bs2=0,bs3=0, bq0=0,bq1=0,bq2=0,bq3=0;

  for (;;) {
    int base = 0;
    if (lane == 0) base = atomicAdd(&g_work, 4);
    base = __shfl_sync(0xffffffffu, base, 0);
    if (base >= NN) break;
    int nend = (base + 4 < NN) ? base + 4 : NN;
    for (int n = base; n < nend; n++) {
      int beg = g_off[n], end = g_off[n+1];
      float sd = g_s[(size_t)n*8 + 4 + head];
      float ax=0.f, ay=0.f, az=0.f, aw=0.f, den=0.f;
      int i = beg;
      for (; i + 4 <= end; i += 4) {
        int s0 = g_csr[i], s1 = g_csr[i+1], s2 = g_csr[i+2], s3 = g_csr[i+3];
        float e0 = g_s[(size_t)s0*8 + head];
        float e1 = g_s[(size_t)s1*8 + head];
        float e2 = g_s[(size_t)s2*8 + head];
        float e3 = g_s[(size_t)s3*8 + head];
        uint2 u0 = *(const uint2*)&g_xs[(size_t)s0*128 + c4];
        uint2 u1 = *(const uint2*)&g_xs[(size_t)s1*128 + c4];
        uint2 u2 = *(const uint2*)&g_xs[(size_t)s2*128 + c4];
        uint2 u3 = *(const uint2*)&g_xs[(size_t)s3*128 + c4];
        e0 += sd; e1 += sd; e2 += sd; e3 += sd;
        e0 = (e0 > 0.f) ? e0 : 0.2f*e0;
        e1 = (e1 > 0.f) ? e1 : 0.2f*e1;
        e2 = (e2 > 0.f) ? e2 : 0.2f*e2;
        e3 = (e3 > 0.f) ? e3 : 0.2f*e3;
        float p0 = __expf(e0), p1 = __expf(e1), p2 = __expf(e2), p3 = __expf(e3);
        den += (p0 + p1) + (p2 + p3);
        float2 a0 = __half22float2(*reinterpret_cast<__half2*>(&u0.x));
        float2 b0 = __half22float2(*reinterpret_cast<__half2*>(&u0.y));
        float2 a1 = __half22float2(*reinterpret_cast<__half2*>(&u1.x));
        float2 b1 = __half22float2(*reinterpret_cast<__half2*>(&u1.y));
        float2 a2 = __half22float2(*reinterpret_cast<__half2*>(&u2.x));
        float2 b2 = __half22float2(*reinterpret_cast<__half2*>(&u2.y));
        float2 a3 = __half22float2(*reinterpret_cast<__half2*>(&u3.x));
        float2 b3 = __half22float2(*reinterpret_cast<__half2*>(&u3.y));
        ax = fmaf(a0.x, p0, ax); ay = fmaf(a0.y, p0, ay);
        az = fmaf(b0.x, p0, az); aw = fmaf(b0.y, p0, aw);
        ax = fmaf(a1.x, p1, ax); ay = fmaf(a1.y, p1, ay);
        az = fmaf(b1.x, p1, az); aw = fmaf(b1.y, p1, aw);
        ax = fmaf(a2.x, p2, ax); ay = fmaf(a2.y, p2, ay);
        az = fmaf(b2.x, p2, az); aw = fmaf(b2.y, p2, aw);
        ax = fmaf(a3.x, p3, ax); ay = fmaf(a3.y, p3, ay);
        az = fmaf(b3.x, p3, az); aw = fmaf(b3.y, p3, aw);
      }
      for (; i < end; i++) {
        int s = g_csr[i];
        float ev = g_s[(size_t)s*8 + head] + sd;
        ev = (ev > 0.f) ? ev : 0.2f*ev;
        float p = __expf(ev);
        den += p;
        uint2 u = *(const uint2*)&g_xs[(size_t)s*128 + c4];
        float2 f0 = __half22float2(*reinterpret_cast<__half2*>(&u.x));
        float2 f1 = __half22float2(*reinterpret_cast<__half2*>(&u.y));
        ax = fmaf(f0.x, p, ax); ay = fmaf(f0.y, p, ay);
        az = fmaf(f1.x, p, az); aw = fmaf(f1.y, p, aw);
      }
      float inv = 1.f / (den + 1e-16f);
      float4 sk = *(const float4*)&g_h[(size_t)n*128 + c4];
      float h0 = ax*inv + cb.x + sk.x;
      float h1 = ay*inv + cb.y + sk.y;
      float h2 = az*inv + cb.z + sk.z;
      float h3 = aw*inv + cb.w + sk.w;
      *(float4*)&g_h[(size_t)n*128 + c4] = make_float4(h0,h1,h2,h3);
      bs0 += h0; bs1 += h1; bs2 += h2; bs3 += h3;
      bq0 += h0*h0; bq1 += h1*h1; bq2 += h2*h2; bq3 += h3*h3;
    }
  }
  atomicAdd(&s_sum[c4+0], bs0); atomicAdd(&s_sum[c4+1], bs1);
  atomicAdd(&s_sum[c4+2], bs2); atomicAdd(&s_sum[c4+3], bs3);
  atomicAdd(&s_sq[c4+0], bq0);  atomicAdd(&s_sq[c4+1], bq1);
  atomicAdd(&s_sq[c4+2], bq2);  atomicAdd(&s_sq[c4+3], bq3);
  __syncthreads();
  if (tid < 128) {
    atomicAdd(&g_bn[tid],       s_sum[tid]);
    atomicAdd(&g_bn[128 + tid], s_sq[tid]);
  }
}

// ---- batchnorm + relu (also emits fp16 copy for next GEMM's A operand) ----
__global__ void __launch_bounds__(256) bn_relu(const float* __restrict__ gamma,
                                               const float* __restrict__ beta,
                                               float* __restrict__ XO) {
  int idx = blockIdx.x*blockDim.x + threadIdx.x;
  if (idx >= NN*32) return;
  int c4 = (idx & 31) * 4;
  const float invN = 1.f / (float)NN;
  float4 h = *(const float4*)&g_h[(size_t)idx*4];
  float hv[4] = {h.x, h.y, h.z, h.w};
  float ov[4];
#pragma unroll
  for (int k = 0; k < 4; k++) {
    int c = c4 + k;
    float mu  = g_bn[c] * invN;
    float var = g_bn[128 + c] * invN - mu*mu;
    float sc  = gamma[c] * rsqrtf(var + 1e-5f);
    float sh  = beta[c] - mu*sc;
    float v = hv[k]*sc + sh;
    ov[k] = v > 0.f ? v : 0.f;
  }
  *(float4*)&XO[(size_t)idx*4] = make_float4(ov[0],ov[1],ov[2],ov[3]);
  *(__half2*)&g_xh[(size_t)idx*4]     = __floats2half2_rn(ov[0], ov[1]);
  *(__half2*)&g_xh[(size_t)idx*4 + 2] = __floats2half2_rn(ov[2], ov[3]);
}

extern "C" void kernel_launch(void* const* d_in, const int* in_sizes, int n_in,
                              void* d_out, int out_size) {
  const float* x0    = (const float*)d_in[0];
  const int*   ei    = (const int*)  d_in[1];
  const float* Wsrc  = (const float*)d_in[2];
  const float* Wdst  = (const float*)d_in[3];
  const float* asrc  = (const float*)d_in[4];
  const float* adst  = (const float*)d_in[5];
  const float* cbias = (const float*)d_in[6];
  const float* linW  = (const float*)d_in[7];
  const float* linb  = (const float*)d_in[8];
  const float* gamma = (const float*)d_in[9];
  const float* beta  = (const float*)d_in[10];
  const float* fcW   = (const float*)d_in[11];
  const float* fcb   = (const float*)d_in[12];
  float* out = (float*)d_out;

  float *xg = 0;
  __half *Bh = 0, *Bl = 0, *Fh = 0, *Fl = 0;
  cudaGetSymbolAddress((void**)&xg, g_x);
  cudaGetSymbolAddress((void**)&Bh, g_Bh);
  cudaGetSymbolAddress((void**)&Bl, g_Bl);
  cudaGetSymbolAddress((void**)&Fh, g_Fh);
  cudaGetSymbolAddress((void**)&Fl, g_Fl);
  cudaFuncSetAttribute(gemm_hmma, cudaFuncAttributeMaxDynamicSharedMemorySize, HM_SMEM);

  const int* src = ei;
  const int* dst = ei + NE;

  // launch index 3 (the one ncu profiles) = gemm_hmma
  k_zero_deg<<<NB, 256>>>();
  k_cvt<<<12500, 256>>>(x0);
  pack_weights<<<134, 256>>>(Wsrc, Wdst, linW, asrc, adst);
  gemm_hmma<<<dim3(2, 782), 256, HM_SMEM>>>(Bh, Bl, nullptr, 0, linb, 1); // profiled
  k_hist<<<(NE+255)/256, 256>>>(dst);
  pack_fc<<<192, 256>>>(fcW);
  k_blockred<<<NB, 256>>>();
  k_scanb<<<1, 512>>>();
  k_off<<<NB, 256>>>();
  k_scatter<<<(NE+255)/256, 256>>>(src, dst);
  att_scores<<<12500, 256>>>(x0);
  gather_combine<<<740, 256>>>(cbias);
  bn_relu<<<12500, 256>>>(gamma, beta, xg);

  pack_weights<<<134, 256>>>(Wsrc + 16384, Wdst + 16384, linW + 16384,
                             asrc + 128, adst + 128);
  gemm_hmma<<<dim3(2, 782), 256, HM_SMEM>>>(Bh, Bl, nullptr, 0, linb + 128, 1);
  att_scores<<<12500, 256>>>(xg);
  gather_combine<<<740, 256>>>(cbias + 128);
  bn_relu<<<12500, 256>>>(gamma + 128, beta + 128, xg);

  gemm_hmma<<<dim3(3, 782), 256, HM_SMEM>>>(Fh, Fl, out, 349, fcb, 0);
}

// round 12
// speedup vs baseline: 1.2993x; 1.0377x over previous
#include <cuda_runtime.h>
#include <cuda_fp16.h>
#include <math.h>
#include <stdint.h>

#define NN 100000
#define NE 1600000
#define DIM 128
#define NB 391   // ceil(NN/256)
#define PADH 72  // padded half-stride; 144B row stride = 9*16B (cp.async-aligned)

typedef unsigned long long ull;

// ---- scratch (device globals: no allocation allowed) ----
__device__ __half g_xs[NN*DIM];   // source-side projection x@Wsrc (fp16)
__device__ __half g_xh[NN*DIM];   // current layer input, fp16 (GEMM A operand)
__device__ float g_h [NN*DIM];    // skip (x@linW+lin_b), later h
__device__ float g_x [NN*DIM];    // layer output ping buffer (fp32)
__device__ float g_s [NN*8];      // per-node attention scores
__device__ __half g_Bh[256*DIM];  // packed [Wsrc|linW] transposed [n][k], fp16 hi
__device__ __half g_Bl[256*DIM];  // fp16 lo residual
__device__ __half g_Fh[384*DIM];  // fcW transposed [n][k] fp16 hi (zero-padded)
__device__ __half g_Fl[384*DIM];  // fcW lo residual
__device__ float g_Batt[2*8*DIM]; // packed (W @ att) vectors, BOTH layers
__device__ float g_bn [2*DIM];    // per-channel sum / sumsq
__device__ int   g_work;          // work-stealing cursor for gather
// CSR (built once; graph fixed across layers)
__device__ int g_deg[NN];
__device__ int g_off[NN+1];
__device__ int g_pos[NN];
__device__ int g_csr[NE];
__device__ int g_bsum[NB];
__device__ int g_bbase[NB];

#define MMA16816(d, a, b0, b1) \
  asm volatile("mma.sync.aligned.m16n8k16.row.col.f32.f16.f16.f32 " \
               "{%0,%1,%2,%3}, {%4,%5,%6,%7}, {%8,%9}, {%0,%1,%2,%3};" \
               : "+f"((d)[0]), "+f"((d)[1]), "+f"((d)[2]), "+f"((d)[3]) \
               : "r"((a)[0]), "r"((a)[1]), "r"((a)[2]), "r"((a)[3]), \
                 "r"(b0), "r"(b1))

__device__ __forceinline__ void cp16(uint32_t smem, const void* g, uint32_t sz) {
  asm volatile("cp.async.cg.shared.global [%0], [%1], 16, %2;"
               :: "r"(smem), "l"(g), "r"(sz) : "memory");
}

// ---- warp helper: 8 attention dots for one node (lane owns channels c4..c4+3)
__device__ __forceinline__ void warp_scores(const float* batt, int lane, int node,
                                            float vx, float vy, float vz, float vw) {
  int c4 = lane*4;
#pragma unroll
  for (int t = 0; t < 8; t++) {
    float4 w = *(const float4*)&batt[t*128 + c4];
    float p = vx*w.x + vy*w.y + vz*w.z + vw*w.w;
#pragma unroll
    for (int off = 16; off; off >>= 1) p += __shfl_xor_sync(0xffffffffu, p, off);
    if (lane == 0) g_s[(size_t)node*8 + t] = p;
  }
}

// ==================== CSR build ====================
__global__ void k_hist(const int* __restrict__ dst) {
  int e = blockIdx.x*blockDim.x + threadIdx.x;
  if (e < NE) atomicAdd(&g_deg[dst[e]], 1);
}
__global__ void k_blockred() {
  __shared__ int sh[256];
  int t = threadIdx.x;
  int i = blockIdx.x*256 + t;
  sh[t] = (i < NN) ? g_deg[i] : 0;
  __syncthreads();
  for (int o = 128; o; o >>= 1) { if (t < o) sh[t] += sh[t+o]; __syncthreads(); }
  if (t == 0) g_bsum[blockIdx.x] = sh[0];
}
__global__ void k_scanb() {
  __shared__ int sh[512];
  int t = threadIdx.x;
  sh[t] = (t < NB) ? g_bsum[t] : 0;
  __syncthreads();
  for (int off = 1; off < 512; off <<= 1) {
    int v = 0;
    if (t >= off) v = sh[t-off];
    __syncthreads();
    sh[t] += v;
    __syncthreads();
  }
  if (t < NB) g_bbase[t] = sh[t] - g_bsum[t];   // exclusive
}
__global__ void k_off() {
  __shared__ int sh[256];
  int t = threadIdx.x;
  int i = blockIdx.x*256 + t;
  int v = (i < NN) ? g_deg[i] : 0;
  sh[t] = v;
  __syncthreads();
  for (int off = 1; off < 256; off <<= 1) {
    int u = 0;
    if (t >= off) u = sh[t-off];
    __syncthreads();
    sh[t] += u;
    __syncthreads();
  }
  int excl = sh[t] - v + g_bbase[blockIdx.x];
  if (i < NN) { g_off[i] = excl; g_pos[i] = excl; }
  if (i == NN-1) g_off[NN] = excl + v;
}
__global__ void k_scatter(const int* __restrict__ src, const int* __restrict__ dst) {
  int e = blockIdx.x*blockDim.x + threadIdx.x;
  if (e >= NE) return;
  int p = atomicAdd(&g_pos[dst[e]], 1);
  g_csr[p] = src[e];
}

// ---- pack att vectors for BOTH layers; zero degree histogram ----
__global__ void pack_att(const float* __restrict__ Wsrc,
                         const float* __restrict__ Wdst,
                         const float* __restrict__ asrc,
                         const float* __restrict__ adst) {
  int idx = blockIdx.x*blockDim.x + threadIdx.x;
  if (idx < NN) g_deg[idx] = 0;
  if (idx < 2048) {
    int layer = idx >> 10;
    int r = idx & 1023;
    int t = r >> 7, k = r & 127;
    int h = t & 3;
    const float* W = ((t < 4) ? Wsrc : Wdst) + layer*16384;
    const float* a = ((t < 4) ? asrc : adst) + layer*128;
    float s = 0.f;
    #pragma unroll
    for (int c = 0; c < 32; c++) s += W[k*128 + h*32 + c] * a[h*32 + c];
    g_Batt[idx] = s;   // layer*1024 + t*128 + k
  }
}

// ---- pack per-layer GEMM weights: fp16 hi/lo transposed [n][k]; zero BN ----
__global__ void pack_weights(const float* __restrict__ Wsrc,
                             const float* __restrict__ linW) {
  int idx = blockIdx.x*blockDim.x + threadIdx.x;
  if (idx == 0) g_work = 0;
  if (idx < 256*DIM) {
    int n = idx >> 7, k = idx & 127;
    float v = (n < 128) ? Wsrc[k*128 + n] : linW[k*128 + (n-128)];
    __half hi = __float2half_rn(v);
    __half lo = __float2half_rn(v - __half2float(hi));
    g_Bh[idx] = hi;
    g_Bl[idx] = lo;
  } else if (idx < 256*DIM + 2*DIM) {
    g_bn[idx - 256*DIM] = 0.f;
  }
}

// ---- pack FC weights (once): fcW [128][349] -> [384][128] fp16 hi/lo ----
__global__ void pack_fc(const float* __restrict__ fcW) {
  int idx = blockIdx.x*blockDim.x + threadIdx.x;
  if (idx >= 384*DIM) return;
  int n = idx >> 7, k = idx & 127;
  float v = (n < 349) ? fcW[k*349 + n] : 0.f;
  __half hi = __float2half_rn(v);
  __half lo = __float2half_rn(v - __half2float(hi));
  g_Fh[idx] = hi;
  g_Fl[idx] = lo;
}

// ---- convert x0 to fp16 + layer-1 attention scores (warp == node) ----
__global__ void __launch_bounds__(256) k_cvt_score(const float* __restrict__ X) {
  int idx = blockIdx.x*blockDim.x + threadIdx.x;
  if (idx >= NN*32) return;
  int node = idx >> 5, lane = idx & 31;
  float4 v = *(const float4*)&X[(size_t)idx*4];
  *(__half2*)&g_xh[(size_t)idx*4]     = __floats2half2_rn(v.x, v.y);
  *(__half2*)&g_xh[(size_t)idx*4 + 2] = __floats2half2_rn(v.z, v.w);
  warp_scores(g_Batt, lane, node, v.x, v.y, v.z, v.w);
}

// ==================== HMMA GEMM: 2-pass (A fp16, W hi/lo), cp.async staging ====
#define HM_SMEM (3*128*PADH*2)   // 55296 B

__global__ void __launch_bounds__(256) gemm_hmma(
    const __half* __restrict__ Bhg, const __half* __restrict__ Blg,
    float* __restrict__ C, int NC,
    const float* __restrict__ bias, int mode)
{
  extern __shared__ __half sh[];
  __half* Ahs = sh;
  __half* Bhs = sh + 128*PADH;
  __half* Bls = sh + 2*128*PADH;
  const int tid = threadIdx.x;
  const int m0 = blockIdx.y * 128;
  const int n0 = blockIdx.x * 128;

  uint32_t sA  = (uint32_t)__cvta_generic_to_shared(Ahs);
  uint32_t sBh = (uint32_t)__cvta_generic_to_shared(Bhs);
  uint32_t sBl = (uint32_t)__cvta_generic_to_shared(Bls);

  const int wid = tid >> 5, t = tid & 31;
  const int wm = (wid & 3) * 32;
  const int wn = (wid >> 2) * 64;
  const int tr = t >> 2, tc = (t & 3) * 2;

  float d[2][8][4];
#pragma unroll
  for (int i = 0; i < 2; i++)
#pragma unroll
    for (int j = 0; j < 8; j++)
#pragma unroll
      for (int q = 0; q < 4; q++) d[i][j][q] = 0.f;

  for (int k0 = 0; k0 < 128; k0 += 64) {
    for (int idx = tid; idx < 1024; idx += 256) {
      int r = idx >> 3, c = (idx & 7) * 8;
      uint32_t off = (uint32_t)(r*PADH + c) * 2;
      int row = m0 + r;
      cp16(sA + off, &g_xh[(size_t)row*128 + k0 + c], (row < NN) ? 16u : 0u);
      cp16(sBh + off, &Bhg[(size_t)(n0 + r)*128 + k0 + c], 16u);
      cp16(sBl + off, &Blg[(size_t)(n0 + r)*128 + k0 + c], 16u);
    }
    asm volatile("cp.async.commit_group;" ::: "memory");
    asm volatile("cp.async.wait_group 0;" ::: "memory");
    __syncthreads();

#pragma unroll
    for (int kk = 0; kk < 4; kk++) {
      const int kc = kk*16 + tc;
      uint32_t ah[2][4];
#pragma unroll
      for (int i = 0; i < 2; i++) {
        int r0 = wm + i*16 + tr;
        ah[i][0] = *(uint32_t*)&Ahs[r0*PADH + kc];
        ah[i][1] = *(uint32_t*)&Ahs[(r0+8)*PADH + kc];
        ah[i][2] = *(uint32_t*)&Ahs[r0*PADH + kc + 8];
        ah[i][3] = *(uint32_t*)&Ahs[(r0+8)*PADH + kc + 8];
      }
#pragma unroll
      for (int j = 0; j < 8; j++) {
        int n = wn + j*8 + tr;
        uint32_t bh0 = *(uint32_t*)&Bhs[n*PADH + kc];
        uint32_t bh1 = *(uint32_t*)&Bhs[n*PADH + kc + 8];
        uint32_t bl0 = *(uint32_t*)&Bls[n*PADH + kc];
        uint32_t bl1 = *(uint32_t*)&Bls[n*PADH + kc + 8];
#pragma unroll
        for (int i = 0; i < 2; i++) {
          MMA16816(d[i][j], ah[i], bh0, bh1);
          MMA16816(d[i][j], ah[i], bl0, bl1);
        }
      }
    }
    __syncthreads();
  }

#pragma unroll
  for (int i = 0; i < 2; i++) {
    int r0 = m0 + wm + i*16 + tr;
#pragma unroll
    for (int j = 0; j < 8; j++) {
      int col = wn + j*8 + tc;
      if (mode == 1) {
        if (n0 == 0) {
          if (r0 < NN)
            *(__half2*)&g_xs[(size_t)r0*128 + col] = __floats2half2_rn(d[i][j][0], d[i][j][1]);
          if (r0 + 8 < NN)
            *(__half2*)&g_xs[(size_t)(r0+8)*128 + col] = __floats2half2_rn(d[i][j][2], d[i][j][3]);
        } else {
          float b0v = bias[col], b1v = bias[col+1];
          if (r0 < NN) {
            g_h[(size_t)r0*128 + col]     = d[i][j][0] + b0v;
            g_h[(size_t)r0*128 + col + 1] = d[i][j][1] + b1v;
          }
          if (r0 + 8 < NN) {
            g_h[(size_t)(r0+8)*128 + col]     = d[i][j][2] + b0v;
            g_h[(size_t)(r0+8)*128 + col + 1] = d[i][j][3] + b1v;
          }
        }
      } else {
        int c = n0 + col;
        if (c < NC) {
          float bv = bias[c];
          if (r0 < NN)     C[(size_t)r0*NC + c]     = d[i][j][0] + bv;
          if (r0 + 8 < NN) C[(size_t)(r0+8)*NC + c] = d[i][j][2] + bv;
        }
        if (c + 1 < NC) {
          float bv = bias[c+1];
          if (r0 < NN)     C[(size_t)r0*NC + c + 1]     = d[i][j][1] + bv;
          if (r0 + 8 < NN) C[(size_t)(r0+8)*NC + c + 1] = d[i][j][3] + bv;
        }
      }
    }
  }
}

// ---- gather: work-stealing warps; BN stats in registers; 8-edge pipeline ----
__global__ void __launch_bounds__(256) gather_combine(const float* __restrict__ cbias) {
  __shared__ float s_sum[128], s_sq[128];
  int tid = threadIdx.x;
  if (tid < 128) { s_sum[tid] = 0.f; s_sq[tid] = 0.f; }
  __syncthreads();
  int lane = tid & 31;
  int head = lane >> 3, c4 = lane*4;
  float4 cb = *(const float4*)&cbias[c4];
  float bs0=0,bs1=0,bs2=0,bs3=0, bq0=0,bq1=0,bq2=0,bq3=0;

  for (;;) {
    int base = 0;
    if (lane == 0) base = atomicAdd(&g_work, 4);
    base = __shfl_sync(0xffffffffu, base, 0);
    if (base >= NN) break;
    int nend = (base + 4 < NN) ? base + 4 : NN;
    for (int n = base; n < nend; n++) {
      int beg = g_off[n], end = g_off[n+1];
      float sd = g_s[(size_t)n*8 + 4 + head];
      float ax=0.f, ay=0.f, az=0.f, aw=0.f, den=0.f;
      int i = beg;
      for (; i + 8 <= end; i += 8) {
        int sI[8];
#pragma unroll
        for (int q = 0; q < 8; q++) sI[q] = g_csr[i+q];
        float ee[8];
#pragma unroll
        for (int q = 0; q < 8; q++) ee[q] = g_s[(size_t)sI[q]*8 + head];
        uint2 uu[8];
#pragma unroll
        for (int q = 0; q < 8; q++) uu[q] = *(const uint2*)&g_xs[(size_t)sI[q]*128 + c4];
#pragma unroll
        for (int q = 0; q < 8; q++) {
          float ev = ee[q] + sd;
          ev = (ev > 0.f) ? ev : 0.2f*ev;
          float p = __expf(ev);
          den += p;
          float2 f0 = __half22float2(*reinterpret_cast<__half2*>(&uu[q].x));
          float2 f1 = __half22float2(*reinterpret_cast<__half2*>(&uu[q].y));
          ax = fmaf(f0.x, p, ax); ay = fmaf(f0.y, p, ay);
          az = fmaf(f1.x, p, az); aw = fmaf(f1.y, p, aw);
        }
      }
      for (; i < end; i++) {
        int s = g_csr[i];
        float ev = g_s[(size_t)s*8 + head] + sd;
        ev = (ev > 0.f) ? ev : 0.2f*ev;
        float p = __expf(ev);
        den += p;
        uint2 u = *(const uint2*)&g_xs[(size_t)s*128 + c4];
        float2 f0 = __half22float2(*reinterpret_cast<__half2*>(&u.x));
        float2 f1 = __half22float2(*reinterpret_cast<__half2*>(&u.y));
        ax = fmaf(f0.x, p, ax); ay = fmaf(f0.y, p, ay);
        az = fmaf(f1.x, p, az); aw = fmaf(f1.y, p, aw);
      }
      float inv = 1.f / (den + 1e-16f);
      float4 sk = *(const float4*)&g_h[(size_t)n*128 + c4];
      float h0 = ax*inv + cb.x + sk.x;
      float h1 = ay*inv + cb.y + sk.y;
      float h2 = az*inv + cb.z + sk.z;
      float h3 = aw*inv + cb.w + sk.w;
      *(float4*)&g_h[(size_t)n*128 + c4] = make_float4(h0,h1,h2,h3);
      bs0 += h0; bs1 += h1; bs2 += h2; bs3 += h3;
      bq0 += h0*h0; bq1 += h1*h1; bq2 += h2*h2; bq3 += h3*h3;
    }
  }
  atomicAdd(&s_sum[c4+0], bs0); atomicAdd(&s_sum[c4+1], bs1);
  atomicAdd(&s_sum[c4+2], bs2); atomicAdd(&s_sum[c4+3], bs3);
  atomicAdd(&s_sq[c4+0], bq0);  atomicAdd(&s_sq[c4+1], bq1);
  atomicAdd(&s_sq[c4+2], bq2);  atomicAdd(&s_sq[c4+3], bq3);
  __syncthreads();
  if (tid < 128) {
    atomicAdd(&g_bn[tid],       s_sum[tid]);
    atomicAdd(&g_bn[128 + tid], s_sq[tid]);
  }
}

// ---- batchnorm + relu (+ fp16 copy; optionally next-layer attention scores) ----
__global__ void __launch_bounds__(256) bn_relu(const float* __restrict__ gamma,
                                               const float* __restrict__ beta,
                                               float* __restrict__ XO, int do_score) {
  int idx = blockIdx.x*blockDim.x + threadIdx.x;
  if (idx >= NN*32) return;
  int node = idx >> 5, lane = idx & 31;
  int c4 = lane * 4;
  const float invN = 1.f / (float)NN;
  float4 h = *(const float4*)&g_h[(size_t)idx*4];
  float hv[4] = {h.x, h.y, h.z, h.w};
  float ov[4];
#pragma unroll
  for (int k = 0; k < 4; k++) {
    int c = c4 + k;
    float mu  = g_bn[c] * invN;
    float var = g_bn[128 + c] * invN - mu*mu;
    float sc  = gamma[c] * rsqrtf(var + 1e-5f);
    float shf = beta[c] - mu*sc;
    float v = hv[k]*sc + shf;
    ov[k] = v > 0.f ? v : 0.f;
  }
  *(float4*)&XO[(size_t)idx*4] = make_float4(ov[0],ov[1],ov[2],ov[3]);
  *(__half2*)&g_xh[(size_t)idx*4]     = __floats2half2_rn(ov[0], ov[1]);
  *(__half2*)&g_xh[(size_t)idx*4 + 2] = __floats2half2_rn(ov[2], ov[3]);
  if (do_score)
    warp_scores(g_Batt + 1024, lane, node, ov[0], ov[1], ov[2], ov[3]);
}

extern "C" void kernel_launch(void* const* d_in, const int* in_sizes, int n_in,
                              void* d_out, int out_size) {
  const float* x0    = (const float*)d_in[0];
  const int*   ei    = (const int*)  d_in[1];
  const float* Wsrc  = (const float*)d_in[2];
  const float* Wdst  = (const float*)d_in[3];
  const float* asrc  = (const float*)d_in[4];
  const float* adst  = (const float*)d_in[5];
  const float* cbias = (const float*)d_in[6];
  const float* linW  = (const float*)d_in[7];
  const float* linb  = (const float*)d_in[8];
  const float* gamma = (const float*)d_in[9];
  const float* beta  = (const float*)d_in[10];
  const float* fcW   = (const float*)d_in[11];
  const float* fcb   = (const float*)d_in[12];
  float* out = (float*)d_out;

  float *xg = 0;
  __half *Bh = 0, *Bl = 0, *Fh = 0, *Fl = 0;
  cudaGetSymbolAddress((void**)&xg, g_x);
  cudaGetSymbolAddress((void**)&Bh, g_Bh);
  cudaGetSymbolAddress((void**)&Bl, g_Bl);
  cudaGetSymbolAddress((void**)&Fh, g_Fh);
  cudaGetSymbolAddress((void**)&Fl, g_Fl);
  cudaFuncSetAttribute(gemm_hmma, cudaFuncAttributeMaxDynamicSharedMemorySize, HM_SMEM);

  const int* src = ei;
  const int* dst = ei + NE;

  // launch index 3 (the one ncu profiles) = gemm_hmma
  pack_att<<<NB, 256>>>(Wsrc, Wdst, asrc, adst);   // both layers' att vecs + zero deg
  pack_weights<<<129, 256>>>(Wsrc, linW);
  k_cvt_score<<<12500, 256>>>(x0);
  gemm_hmma<<<dim3(2, 782), 256, HM_SMEM>>>(Bh, Bl, nullptr, 0, linb, 1); // profiled
  k_hist<<<(NE+255)/256, 256>>>(dst);
  pack_fc<<<192, 256>>>(fcW);
  k_blockred<<<NB, 256>>>();
  k_scanb<<<1, 512>>>();
  k_off<<<NB, 256>>>();
  k_scatter<<<(NE+255)/256, 256>>>(src, dst);
  gather_combine<<<740, 256>>>(cbias);
  bn_relu<<<12500, 256>>>(gamma, beta, xg, 1);     // + layer-2 scores

  pack_weights<<<129, 256>>>(Wsrc + 16384, linW + 16384);
  gemm_hmma<<<dim3(2, 782), 256, HM_SMEM>>>(Bh, Bl, nullptr, 0, linb + 128, 1);
  gather_combine<<<740, 256>>>(cbias + 128);
  bn_relu<<<12500, 256>>>(gamma + 128, beta + 128, xg, 0);

  gemm_hmma<<<dim3(3, 782), 256, HM_SMEM>>>(Fh, Fl, out, 349, fcb, 0);
}

// round 13
// speedup vs baseline: 1.3319x; 1.0251x over previous
#include <cuda_runtime.h>
#include <cuda_fp16.h>
#include <math.h>
#include <stdint.h>

#define NN 100000
#define NE 1600000
#define DIM 128
#define NB 391   // ceil(NN/256)
#define PADH 72  // padded half-stride; 144B row stride = 9*16B (cp.async-aligned)
#define ST (128*PADH)   // halves per SMEM tile

typedef unsigned long long ull;

// ---- scratch (device globals: no allocation allowed) ----
__device__ __half g_xs[NN*DIM];   // source-side projection x@Wsrc (fp16)
__device__ __half g_xh[NN*DIM];   // current layer input, fp16 (GEMM A operand)
__device__ float g_h [NN*DIM];    // skip (x@linW+lin_b), later h
__device__ float g_s [NN*8];      // per-node attention scores
__device__ __half g_Bh[256*DIM];  // packed [Wsrc|linW] transposed [n][k], fp16 hi
__device__ __half g_Bl[256*DIM];  // fp16 lo residual
__device__ __half g_Fh[384*DIM];  // fcW transposed [n][k] fp16 hi (zero-padded)
__device__ __half g_Fl[384*DIM];  // fcW lo residual
__device__ float g_Batt[2*8*DIM]; // packed (W @ att) vectors, BOTH layers
__device__ float g_bn [2*DIM];    // per-channel sum / sumsq
__device__ int   g_work;          // work-stealing cursor for gather
// CSR (built once; graph fixed across layers)
__device__ int g_deg[NN];
__device__ int g_off[NN+1];
__device__ int g_pos[NN];
__device__ int g_csr[NE];
__device__ int g_bsum[NB];
__device__ int g_bbase[NB];

#define MMA16816(d, a, b0, b1) \
  asm volatile("mma.sync.aligned.m16n8k16.row.col.f32.f16.f16.f32 " \
               "{%0,%1,%2,%3}, {%4,%5,%6,%7}, {%8,%9}, {%0,%1,%2,%3};" \
               : "+f"((d)[0]), "+f"((d)[1]), "+f"((d)[2]), "+f"((d)[3]) \
               : "r"((a)[0]), "r"((a)[1]), "r"((a)[2]), "r"((a)[3]), \
                 "r"(b0), "r"(b1))

__device__ __forceinline__ void cp16(uint32_t smem, const void* g, uint32_t sz) {
  asm volatile("cp.async.cg.shared.global [%0], [%1], 16, %2;"
               :: "r"(smem), "l"(g), "r"(sz) : "memory");
}

// ---- warp helper: 8 attention dots for one node (lane owns channels c4..c4+3)
__device__ __forceinline__ void warp_scores(const float* batt, int lane, int node,
                                            float vx, float vy, float vz, float vw) {
  int c4 = lane*4;
#pragma unroll
  for (int t = 0; t < 8; t++) {
    float4 w = *(const float4*)&batt[t*128 + c4];
    float p = vx*w.x + vy*w.y + vz*w.z + vw*w.w;
#pragma unroll
    for (int off = 16; off; off >>= 1) p += __shfl_xor_sync(0xffffffffu, p, off);
    if (lane == 0) g_s[(size_t)node*8 + t] = p;
  }
}

// ==================== CSR build ====================
__global__ void k_hist(const int* __restrict__ dst) {
  int e = blockIdx.x*blockDim.x + threadIdx.x;
  if (e < NE) atomicAdd(&g_deg[dst[e]], 1);
}
__global__ void k_blockred() {
  __shared__ int sh[256];
  int t = threadIdx.x;
  int i = blockIdx.x*256 + t;
  sh[t] = (i < NN) ? g_deg[i] : 0;
  __syncthreads();
  for (int o = 128; o; o >>= 1) { if (t < o) sh[t] += sh[t+o]; __syncthreads(); }
  if (t == 0) g_bsum[blockIdx.x] = sh[0];
}
__global__ void k_scanb() {
  __shared__ int sh[512];
  int t = threadIdx.x;
  sh[t] = (t < NB) ? g_bsum[t] : 0;
  __syncthreads();
  for (int off = 1; off < 512; off <<= 1) {
    int v = 0;
    if (t >= off) v = sh[t-off];
    __syncthreads();
    sh[t] += v;
    __syncthreads();
  }
  if (t < NB) g_bbase[t] = sh[t] - g_bsum[t];   // exclusive
}
__global__ void k_off() {
  __shared__ int sh[256];
  int t = threadIdx.x;
  int i = blockIdx.x*256 + t;
  int v = (i < NN) ? g_deg[i] : 0;
  sh[t] = v;
  __syncthreads();
  for (int off = 1; off < 256; off <<= 1) {
    int u = 0;
    if (t >= off) u = sh[t-off];
    __syncthreads();
    sh[t] += u;
    __syncthreads();
  }
  int excl = sh[t] - v + g_bbase[blockIdx.x];
  if (i < NN) { g_off[i] = excl; g_pos[i] = excl; }
  if (i == NN-1) g_off[NN] = excl + v;
}
__global__ void k_scatter(const int* __restrict__ src, const int* __restrict__ dst) {
  int e = blockIdx.x*blockDim.x + threadIdx.x;
  if (e >= NE) return;
  int p = atomicAdd(&g_pos[dst[e]], 1);
  g_csr[p] = src[e];
}

// ---- pack att vectors for BOTH layers; zero degree histogram ----
__global__ void pack_att(const float* __restrict__ Wsrc,
                         const float* __restrict__ Wdst,
                         const float* __restrict__ asrc,
                         const float* __restrict__ adst) {
  int idx = blockIdx.x*blockDim.x + threadIdx.x;
  if (idx < NN) g_deg[idx] = 0;
  if (idx < 2048) {
    int layer = idx >> 10;
    int r = idx & 1023;
    int t = r >> 7, k = r & 127;
    int h = t & 3;
    const float* W = ((t < 4) ? Wsrc : Wdst) + layer*16384;
    const float* a = ((t < 4) ? asrc : adst) + layer*128;
    float s = 0.f;
    #pragma unroll
    for (int c = 0; c < 32; c++) s += W[k*128 + h*32 + c] * a[h*32 + c];
    g_Batt[idx] = s;   // layer*1024 + t*128 + k
  }
}

// ---- pack per-layer GEMM weights: fp16 hi/lo transposed [n][k]; zero BN ----
__global__ void pack_weights(const float* __restrict__ Wsrc,
                             const float* __restrict__ linW) {
  int idx = blockIdx.x*blockDim.x + threadIdx.x;
  if (idx == 0) g_work = 0;
  if (idx < 256*DIM) {
    int n = idx >> 7, k = idx & 127;
    float v = (n < 128) ? Wsrc[k*128 + n] : linW[k*128 + (n-128)];
    __half hi = __float2half_rn(v);
    __half lo = __float2half_rn(v - __half2float(hi));
    g_Bh[idx] = hi;
    g_Bl[idx] = lo;
  } else if (idx < 256*DIM + 2*DIM) {
    g_bn[idx - 256*DIM] = 0.f;
  }
}

// ---- pack FC weights (once): fcW [128][349] -> [384][128] fp16 hi/lo ----
__global__ void pack_fc(const float* __restrict__ fcW) {
  int idx = blockIdx.x*blockDim.x + threadIdx.x;
  if (idx >= 384*DIM) return;
  int n = idx >> 7, k = idx & 127;
  float v = (n < 349) ? fcW[k*349 + n] : 0.f;
  __half hi = __float2half_rn(v);
  __half lo = __float2half_rn(v - __half2float(hi));
  g_Fh[idx] = hi;
  g_Fl[idx] = lo;
}

// ---- convert x0 to fp16 + layer-1 attention scores (warp == node) ----
__global__ void __launch_bounds__(256) k_cvt_score(const float* __restrict__ X) {
  int idx = blockIdx.x*blockDim.x + threadIdx.x;
  if (idx >= NN*32) return;
  int node = idx >> 5, lane = idx & 31;
  float4 v = *(const float4*)&X[(size_t)idx*4];
  *(__half2*)&g_xh[(size_t)idx*4]     = __floats2half2_rn(v.x, v.y);
  *(__half2*)&g_xh[(size_t)idx*4 + 2] = __floats2half2_rn(v.z, v.w);
  warp_scores(g_Batt, lane, node, v.x, v.y, v.z, v.w);
}

// ==================== HMMA GEMM: 2-pass, double-buffered K slices ====
#define HM_SMEM (6*ST*2)   // 110592 B (2 stages x {A,Bh,Bl})

__device__ __forceinline__ void hm_stage(int tid, int m0, int n0, int k0,
    uint32_t sA, uint32_t sBh, uint32_t sBl,
    const __half* __restrict__ Bhg, const __half* __restrict__ Blg) {
  for (int idx = tid; idx < 1024; idx += 256) {
    int r = idx >> 3, c = (idx & 7) * 8;
    uint32_t off = (uint32_t)(r*PADH + c) * 2;
    int row = m0 + r;
    cp16(sA + off, &g_xh[(size_t)row*128 + k0 + c], (row < NN) ? 16u : 0u);
    cp16(sBh + off, &Bhg[(size_t)(n0 + r)*128 + k0 + c], 16u);
    cp16(sBl + off, &Blg[(size_t)(n0 + r)*128 + k0 + c], 16u);
  }
  asm volatile("cp.async.commit_group;" ::: "memory");
}

__device__ __forceinline__ void hm_compute(const __half* Ahs, const __half* Bhs,
    const __half* Bls, int wm, int wn, int tr, int tc, float d[2][8][4]) {
#pragma unroll
  for (int kk = 0; kk < 4; kk++) {
    const int kc = kk*16 + tc;
    uint32_t ah[2][4];
#pragma unroll
    for (int i = 0; i < 2; i++) {
      int r0 = wm + i*16 + tr;
      ah[i][0] = *(const uint32_t*)&Ahs[r0*PADH + kc];
      ah[i][1] = *(const uint32_t*)&Ahs[(r0+8)*PADH + kc];
      ah[i][2] = *(const uint32_t*)&Ahs[r0*PADH + kc + 8];
      ah[i][3] = *(const uint32_t*)&Ahs[(r0+8)*PADH + kc + 8];
    }
#pragma unroll
    for (int j = 0; j < 8; j++) {
      int n = wn + j*8 + tr;
      uint32_t bh0 = *(const uint32_t*)&Bhs[n*PADH + kc];
      uint32_t bh1 = *(const uint32_t*)&Bhs[n*PADH + kc + 8];
      uint32_t bl0 = *(const uint32_t*)&Bls[n*PADH + kc];
      uint32_t bl1 = *(const uint32_t*)&Bls[n*PADH + kc + 8];
#pragma unroll
      for (int i = 0; i < 2; i++) {
        MMA16816(d[i][j], ah[i], bh0, bh1);
        MMA16816(d[i][j], ah[i], bl0, bl1);
      }
    }
  }
}

__global__ void __launch_bounds__(256) gemm_hmma(
    const __half* __restrict__ Bhg, const __half* __restrict__ Blg,
    float* __restrict__ C, int NC,
    const float* __restrict__ bias, int mode)
{
  extern __shared__ __half sh[];
  const int tid = threadIdx.x;
  const int m0 = blockIdx.y * 128;
  const int n0 = blockIdx.x * 128;
  uint32_t s0 = (uint32_t)__cvta_generic_to_shared(sh);

  const int wid = tid >> 5, t = tid & 31;
  const int wm = (wid & 3) * 32;
  const int wn = (wid >> 2) * 64;
  const int tr = t >> 2, tc = (t & 3) * 2;

  float d[2][8][4];
#pragma unroll
  for (int i = 0; i < 2; i++)
#pragma unroll
    for (int j = 0; j < 8; j++)
#pragma unroll
      for (int q = 0; q < 4; q++) d[i][j][q] = 0.f;

  // issue both K-slice loads immediately (2 cp.async groups)
  hm_stage(tid, m0, n0, 0,  s0,            s0 + ST*2,   s0 + 2*ST*2, Bhg, Blg);
  hm_stage(tid, m0, n0, 64, s0 + 3*ST*2,   s0 + 4*ST*2, s0 + 5*ST*2, Bhg, Blg);

  asm volatile("cp.async.wait_group 1;" ::: "memory");
  __syncthreads();
  hm_compute(sh, sh + ST, sh + 2*ST, wm, wn, tr, tc, d);

  asm volatile("cp.async.wait_group 0;" ::: "memory");
  __syncthreads();
  hm_compute(sh + 3*ST, sh + 4*ST, sh + 5*ST, wm, wn, tr, tc, d);

#pragma unroll
  for (int i = 0; i < 2; i++) {
    int r0 = m0 + wm + i*16 + tr;
#pragma unroll
    for (int j = 0; j < 8; j++) {
      int col = wn + j*8 + tc;
      if (mode == 1) {
        if (n0 == 0) {
          if (r0 < NN)
            *(__half2*)&g_xs[(size_t)r0*128 + col] = __floats2half2_rn(d[i][j][0], d[i][j][1]);
          if (r0 + 8 < NN)
            *(__half2*)&g_xs[(size_t)(r0+8)*128 + col] = __floats2half2_rn(d[i][j][2], d[i][j][3]);
        } else {
          float b0v = bias[col], b1v = bias[col+1];
          if (r0 < NN) {
            g_h[(size_t)r0*128 + col]     = d[i][j][0] + b0v;
            g_h[(size_t)r0*128 + col + 1] = d[i][j][1] + b1v;
          }
          if (r0 + 8 < NN) {
            g_h[(size_t)(r0+8)*128 + col]     = d[i][j][2] + b0v;
            g_h[(size_t)(r0+8)*128 + col + 1] = d[i][j][3] + b1v;
          }
        }
      } else {
        int c = n0 + col;
        if (c < NC) {
          float bv = bias[c];
          if (r0 < NN)     C[(size_t)r0*NC + c]     = d[i][j][0] + bv;
          if (r0 + 8 < NN) C[(size_t)(r0+8)*NC + c] = d[i][j][2] + bv;
        }
        if (c + 1 < NC) {
          float bv = bias[c+1];
          if (r0 < NN)     C[(size_t)r0*NC + c + 1]     = d[i][j][1] + bv;
          if (r0 + 8 < NN) C[(size_t)(r0+8)*NC + c + 1] = d[i][j][3] + bv;
        }
      }
    }
  }
}

// ---- gather: work-stealing warps; BN stats in registers; 8-edge pipeline ----
__global__ void __launch_bounds__(256) gather_combine(const float* __restrict__ cbias) {
  __shared__ float s_sum[128], s_sq[128];
  int tid = threadIdx.x;
  if (tid < 128) { s_sum[tid] = 0.f; s_sq[tid] = 0.f; }
  __syncthreads();
  int lane = tid & 31;
  int head = lane >> 3, c4 = lane*4;
  float4 cb = *(const float4*)&cbias[c4];
  float bs0=0,bs1=0,bs2=0,bs3=0, bq0=0,bq1=0,bq2=0,bq3=0;

  for (;;) {
    int base = 0;
    if (lane == 0) base = atomicAdd(&g_work, 4);
    base = __shfl_sync(0xffffffffu, base, 0);
    if (base >= NN) break;
    int nend = (base + 4 < NN) ? base + 4 : NN;
    for (int n = base; n < nend; n++) {
      int beg = g_off[n], end = g_off[n+1];
      float sd = g_s[(size_t)n*8 + 4 + head];
      float ax=0.f, ay=0.f, az=0.f, aw=0.f, den=0.f;
      int i = beg;
      for (; i + 8 <= end; i += 8) {
        int sI[8];
#pragma unroll
        for (int q = 0; q < 8; q++) sI[q] = g_csr[i+q];
        float ee[8];
#pragma unroll
        for (int q = 0; q < 8; q++) ee[q] = g_s[(size_t)sI[q]*8 + head];
        uint2 uu[8];
#pragma unroll
        for (int q = 0; q < 8; q++) uu[q] = *(const uint2*)&g_xs[(size_t)sI[q]*128 + c4];
#pragma unroll
        for (int q = 0; q < 8; q++) {
          float ev = ee[q] + sd;
          ev = (ev > 0.f) ? ev : 0.2f*ev;
          float p = __expf(ev);
          den += p;
          float2 f0 = __half22float2(*reinterpret_cast<__half2*>(&uu[q].x));
          float2 f1 = __half22float2(*reinterpret_cast<__half2*>(&uu[q].y));
          ax = fmaf(f0.x, p, ax); ay = fmaf(f0.y, p, ay);
          az = fmaf(f1.x, p, az); aw = fmaf(f1.y, p, aw);
        }
      }
      for (; i < end; i++) {
        int s = g_csr[i];
        float ev = g_s[(size_t)s*8 + head] + sd;
        ev = (ev > 0.f) ? ev : 0.2f*ev;
        float p = __expf(ev);
        den += p;
        uint2 u = *(const uint2*)&g_xs[(size_t)s*128 + c4];
        float2 f0 = __half22float2(*reinterpret_cast<__half2*>(&u.x));
        float2 f1 = __half22float2(*reinterpret_cast<__half2*>(&u.y));
        ax = fmaf(f0.x, p, ax); ay = fmaf(f0.y, p, ay);
        az = fmaf(f1.x, p, az); aw = fmaf(f1.y, p, aw);
      }
      float inv = 1.f / (den + 1e-16f);
      float4 sk = *(const float4*)&g_h[(size_t)n*128 + c4];
      float h0 = ax*inv + cb.x + sk.x;
      float h1 = ay*inv + cb.y + sk.y;
      float h2 = az*inv + cb.z + sk.z;
      float h3 = aw*inv + cb.w + sk.w;
      *(float4*)&g_h[(size_t)n*128 + c4] = make_float4(h0,h1,h2,h3);
      bs0 += h0; bs1 += h1; bs2 += h2; bs3 += h3;
      bq0 += h0*h0; bq1 += h1*h1; bq2 += h2*h2; bq3 += h3*h3;
    }
  }
  atomicAdd(&s_sum[c4+0], bs0); atomicAdd(&s_sum[c4+1], bs1);
  atomicAdd(&s_sum[c4+2], bs2); atomicAdd(&s_sum[c4+3], bs3);
  atomicAdd(&s_sq[c4+0], bq0);  atomicAdd(&s_sq[c4+1], bq1);
  atomicAdd(&s_sq[c4+2], bq2);  atomicAdd(&s_sq[c4+3], bq3);
  __syncthreads();
  if (tid < 128) {
    atomicAdd(&g_bn[tid],       s_sum[tid]);
    atomicAdd(&g_bn[128 + tid], s_sq[tid]);
  }
}

// ---- batchnorm + relu -> fp16 next-layer input (+ optional next-layer scores) ----
__global__ void __launch_bounds__(256) bn_relu(const float* __restrict__ gamma,
                                               const float* __restrict__ beta,
                                               int do_score) {
  int idx = blockIdx.x*blockDim.x + threadIdx.x;
  if (idx >= NN*32) return;
  int node = idx >> 5, lane = idx & 31;
  int c4 = lane * 4;
  const float invN = 1.f / (float)NN;
  float4 h = *(const float4*)&g_h[(size_t)idx*4];
  float hv[4] = {h.x, h.y, h.z, h.w};
  float ov[4];
#pragma unroll
  for (int k = 0; k < 4; k++) {
    int c = c4 + k;
    float mu  = g_bn[c] * invN;
    float var = g_bn[128 + c] * invN - mu*mu;
    float sc  = gamma[c] * rsqrtf(var + 1e-5f);
    float shf = beta[c] - mu*sc;
    float v = hv[k]*sc + shf;
    ov[k] = v > 0.f ? v : 0.f;
  }
  *(__half2*)&g_xh[(size_t)idx*4]     = __floats2half2_rn(ov[0], ov[1]);
  *(__half2*)&g_xh[(size_t)idx*4 + 2] = __floats2half2_rn(ov[2], ov[3]);
  if (do_score)
    warp_scores(g_Batt + 1024, lane, node, ov[0], ov[1], ov[2], ov[3]);
}

extern "C" void kernel_launch(void* const* d_in, const int* in_sizes, int n_in,
                              void* d_out, int out_size) {
  const float* x0    = (const float*)d_in[0];
  const int*   ei    = (const int*)  d_in[1];
  const float* Wsrc  = (const float*)d_in[2];
  const float* Wdst  = (const float*)d_in[3];
  const float* asrc  = (const float*)d_in[4];
  const float* adst  = (const float*)d_in[5];
  const float* cbias = (const float*)d_in[6];
  const float* linW  = (const float*)d_in[7];
  const float* linb  = (const float*)d_in[8];
  const float* gamma = (const float*)d_in[9];
  const float* beta  = (const float*)d_in[10];
  const float* fcW   = (const float*)d_in[11];
  const float* fcb   = (const float*)d_in[12];
  float* out = (float*)d_out;

  __half *Bh = 0, *Bl = 0, *Fh = 0, *Fl = 0;
  cudaGetSymbolAddress((void**)&Bh, g_Bh);
  cudaGetSymbolAddress((void**)&Bl, g_Bl);
  cudaGetSymbolAddress((void**)&Fh, g_Fh);
  cudaGetSymbolAddress((void**)&Fl, g_Fl);
  cudaFuncSetAttribute(gemm_hmma, cudaFuncAttributeMaxDynamicSharedMemorySize, HM_SMEM);

  const int* src = ei;
  const int* dst = ei + NE;

  // launch index 3 (the one ncu profiles) = gemm_hmma
  pack_att<<<NB, 256>>>(Wsrc, Wdst, asrc, adst);   // both layers' att vecs + zero deg
  pack_weights<<<129, 256>>>(Wsrc, linW);
  k_cvt_score<<<12500, 256>>>(x0);
  gemm_hmma<<<dim3(2, 782), 256, HM_SMEM>>>(Bh, Bl, nullptr, 0, linb, 1); // profiled
  k_hist<<<(NE+255)/256, 256>>>(dst);
  pack_fc<<<192, 256>>>(fcW);
  k_blockred<<<NB, 256>>>();
  k_scanb<<<1, 512>>>();
  k_off<<<NB, 256>>>();
  k_scatter<<<(NE+255)/256, 256>>>(src, dst);
  gather_combine<<<740, 256>>>(cbias);
  bn_relu<<<12500, 256>>>(gamma, beta, 1);     // + layer-2 scores

  pack_weights<<<129, 256>>>(Wsrc + 16384, linW + 16384);
  gemm_hmma<<<dim3(2, 782), 256, HM_SMEM>>>(Bh, Bl, nullptr, 0, linb + 128, 1);
  gather_combine<<<740, 256>>>(cbias + 128);
  bn_relu<<<12500, 256>>>(gamma + 128, beta + 128, 0);

  gemm_hmma<<<dim3(3, 782), 256, HM_SMEM>>>(Fh, Fl, out, 349, fcb, 0);
}